// round 9
// baseline (speedup 1.0000x reference)
#include <cuda_runtime.h>
#include <math.h>

// ---------------------------------------------------------------------------
// GlobalLocalAwareEncoder — truncated-dependency implementation.
// T1: dilated segments (64/128/256) never cross 256-token boundaries ->
//     output token 0 depends only on tokens [0,256) per batch.
// T2: layer 2 is last -> only token 0 per batch feeds output; layer-2 tail
//     fused into one 16-CTA kernel.
// Attention configs write disjoint buffers (t==h mod r); Wo sums with masks.
// Attention runs on tf32 m16n8k8 tensor cores (128-thread CTAs, 4 warps).
// All GEMMs use BN=128 CTA tiles. LayerNorm is FUSED into the consuming
// GEMM's A-prologue (per-CTA row stats) — no standalone LN launches.
// ---------------------------------------------------------------------------

#define BATCH   16
#define SEQ     256
#define TOK     (BATCH * SEQ)   // 4096
#define DIM     256
#define HEADS   8
#define HDIM    32
#define FFN_DIM 1024
#define INDIM   512
#define NCTX    4095

__device__ float g_x  [TOK * DIM];
__device__ float g_h  [TOK * DIM];     // attention b2 scratch
__device__ float g_q  [TOK * DIM];
__device__ float g_k  [TOK * DIM];
__device__ float g_v  [TOK * DIM];
__device__ float g_acc[TOK * DIM];     // attention b1 scratch
__device__ float g_ffn[TOK * FFN_DIM]; // attention b4 scratch + FFN hidden

__device__ __forceinline__ float gelu_tanh(float x) {
    float x3 = x * x * x;
    return 0.5f * x * (1.0f + tanhf(0.7978845608028654f * (x + 0.044715f * x3)));
}

__device__ __forceinline__ unsigned f2tf32(float f) {
    unsigned u;
    asm("cvt.rna.tf32.f32 %0, %1;" : "=r"(u) : "f"(f));
    return u;
}

__device__ __forceinline__ void mma_tf32(float* d, uint4 a, unsigned b0, unsigned b1) {
    asm volatile(
        "mma.sync.aligned.m16n8k8.row.col.f32.tf32.tf32.f32 "
        "{%0,%1,%2,%3}, {%4,%5,%6,%7}, {%8,%9}, {%0,%1,%2,%3};"
        : "+f"(d[0]), "+f"(d[1]), "+f"(d[2]), "+f"(d[3])
        : "r"(a.x), "r"(a.y), "r"(a.z), "r"(a.w), "r"(b0), "r"(b1));
}

__device__ __forceinline__ float wred_sum(float v) {
#pragma unroll
    for (int o = 16; o > 0; o >>= 1) v += __shfl_xor_sync(0xffffffffu, v, o);
    return v;
}

// positional encoding value for (token row, channel col), dim=256
__device__ __forceinline__ float pe_val(int row, int col,
                                        const float* __restrict__ tpos,
                                        const float* __restrict__ cpos) {
    int b = row >> 8, s = row & 255;
    const float* pp = (s == 0) ? (tpos + (size_t)b * 2)
                               : (cpos + ((size_t)b * NCTX + (s - 1)) * 2);
    float pos = (col < 128) ? pp[0] : pp[1];
    int dd = col & 127;
    int i  = dd & 63;
    float omega = expf(-(float)i * (9.210340371976184f / 64.0f));
    float ang = pos * omega;
    return (dd < 64) ? sinf(ang) : cosf(ang);
}

// ---------------------------------------------------------------------------
// tf32 MMA GEMM. C[4096,N] = A[4096,K] @ B[K,N], B row-major.
// CTA tile 64(M) x BN(N), BK=16, double-buffered. 8 warps, warp 32 x (BN/4).
// EPI: 0 store / 2 gelu(v+bias) / 3 v+res(+bias) / 5 v+bias+0.3*posenc
// ASUM3: A(t,k) = A1 + [t==h mod2]*A2 + [t==h mod4]*A4, h=k>>5.
// LNA:   A-rows are LayerNorm'ed on the fly: (x-mu)*rstd*lnsc[k]+lnbi[k].
//        Requires K == 256. Per-CTA stats prologue over its 64 rows.
// ---------------------------------------------------------------------------
template<int EPI, int BN, bool GATHER, bool ASUM3, bool LNA>
__global__ __launch_bounds__(256)
void mma_gemm(const float* __restrict__ A,
              const float* __restrict__ A2, const float* __restrict__ A4,
              const float* __restrict__ B0, const float* __restrict__ B1,
              const float* __restrict__ B2,
              const float* __restrict__ bias, const float* __restrict__ res,
              float* __restrict__ C0, float* __restrict__ C1, float* __restrict__ C2,
              int N, int K,
              const float* __restrict__ tfeat, const float* __restrict__ cfeat,
              const float* __restrict__ tpos,  const float* __restrict__ cpos,
              const float* __restrict__ lnsc,  const float* __restrict__ lnbi)
{
    constexpr int BSST = BN + 8;
    constexpr int NF   = BN / 32;
    constexpr int NBL  = BN / 16;

    __shared__ unsigned As[2][1024];
    __shared__ unsigned Bs[2][16 * BSST];
    __shared__ float s_mu[64], s_rs[64];

    const int z = blockIdx.z;
    const float* B = (z == 0) ? B0 : (z == 1) ? B1 : B2;
    float*       C = (z == 0) ? C0 : (z == 1) ? C1 : C2;

    const int t    = threadIdx.x;
    const int lane = t & 31;
    const int warp = t >> 5;
    const int wm   = warp >> 2;
    const int wn   = warp & 3;
    const int gid  = lane >> 2;
    const int tig  = lane & 3;

    const int bm = blockIdx.y * 64;
    const int bn = blockIdx.x * BN;

    const int a_mf = t >> 6;
    const int al   = t & 31;
    const int arow = a_mf * 16 + (al >> 2);
    const int acol = ((t >> 5) & 1) * 8 + (al & 3);

    const int r0row = bm + arow;
    const int r1row = r0row + 8;

    const float *a1p0, *a1p1;
    const float *a2p0 = nullptr, *a2p1 = nullptr, *a4p0 = nullptr, *a4p1 = nullptr;
    if (GATHER) {
        int b0i = r0row >> 8, s0 = r0row & 255;
        int b1i = r1row >> 8, s1 = r1row & 255;
        a1p0 = (s0 == 0) ? (tfeat + (size_t)b0i * INDIM)
                         : (cfeat + ((size_t)b0i * NCTX + (s0 - 1)) * INDIM);
        a1p1 = (s1 == 0) ? (tfeat + (size_t)b1i * INDIM)
                         : (cfeat + ((size_t)b1i * NCTX + (s1 - 1)) * INDIM);
    } else {
        a1p0 = A + (size_t)r0row * K;
        a1p1 = A + (size_t)r1row * K;
        if (ASUM3) {
            a2p0 = A2 + (size_t)r0row * K;  a2p1 = A2 + (size_t)r1row * K;
            a4p0 = A4 + (size_t)r0row * K;  a4p1 = A4 + (size_t)r1row * K;
        }
    }

    // ---- LNA prologue: per-CTA row stats (K must be 256) ----
    float mu0 = 0.f, rs0 = 1.f, mu1 = 0.f, rs1 = 1.f;
    if (LNA) {
#pragma unroll
        for (int rr = 0; rr < 8; rr++) {
            int row = warp * 8 + rr;
            const float4* xp = (const float4*)(A + (size_t)(bm + row) * 256);
            float4 u0 = xp[lane];
            float4 u1 = xp[lane + 32];
            float sum = u0.x + u0.y + u0.z + u0.w + u1.x + u1.y + u1.z + u1.w;
            float sq  = u0.x * u0.x + u0.y * u0.y + u0.z * u0.z + u0.w * u0.w
                      + u1.x * u1.x + u1.y * u1.y + u1.z * u1.z + u1.w * u1.w;
            sum = wred_sum(sum);
            sq  = wred_sum(sq);
            if (lane == 0) {
                float mu  = sum * (1.0f / 256.0f);
                float var = sq * (1.0f / 256.0f) - mu * mu;
                s_mu[row] = mu;
                s_rs[row] = rsqrtf(var + 1e-5f);
            }
        }
        __syncthreads();
        mu0 = s_mu[arow];     rs0 = s_rs[arow];
        mu1 = s_mu[arow + 8]; rs1 = s_rs[arow + 8];
    }

    int b_goff[NBL], b_soff[NBL];
#pragma unroll
    for (int i = 0; i < NBL; i++) {
        int idx = t + 256 * i;
        int kk  = idx / BN;
        int n   = idx % BN;
        b_goff[i] = kk * N + bn + n;
        b_soff[i] = kk * BSST + n;
    }

    float accd[2][NF][4];
#pragma unroll
    for (int mf = 0; mf < 2; mf++)
#pragma unroll
        for (int nf = 0; nf < NF; nf++)
#pragma unroll
            for (int r = 0; r < 4; r++) accd[mf][nf][r] = 0.f;

    const int nchunks = K >> 4;
    float pa0, pa1, pa2, pa3;
    float pb[NBL];

    auto loadA = [&](int k0) {
        if (LNA) {
            int kc = k0 + acol;
            float sc0 = lnsc[kc],     bi0 = lnbi[kc];
            float sc4 = lnsc[kc + 4], bi4 = lnbi[kc + 4];
            pa0 = (a1p0[kc]     - mu0) * rs0 * sc0 + bi0;
            pa1 = (a1p1[kc]     - mu1) * rs1 * sc0 + bi0;
            pa2 = (a1p0[kc + 4] - mu0) * rs0 * sc4 + bi4;
            pa3 = (a1p1[kc + 4] - mu1) * rs1 * sc4 + bi4;
        } else if (ASUM3) {
            int kc  = k0 + acol;
            int hh  = kc >> 5;
            bool m20 = ((r0row ^ hh) & 1) == 0, m40 = ((r0row ^ hh) & 3) == 0;
            bool m21 = ((r1row ^ hh) & 1) == 0, m41 = ((r1row ^ hh) & 3) == 0;
            pa0 = a1p0[kc]     + (m20 ? a2p0[kc]     : 0.f) + (m40 ? a4p0[kc]     : 0.f);
            pa1 = a1p1[kc]     + (m21 ? a2p1[kc]     : 0.f) + (m41 ? a4p1[kc]     : 0.f);
            pa2 = a1p0[kc + 4] + (m20 ? a2p0[kc + 4] : 0.f) + (m40 ? a4p0[kc + 4] : 0.f);
            pa3 = a1p1[kc + 4] + (m21 ? a2p1[kc + 4] : 0.f) + (m41 ? a4p1[kc + 4] : 0.f);
        } else {
            pa0 = a1p0[k0 + acol];     pa1 = a1p1[k0 + acol];
            pa2 = a1p0[k0 + acol + 4]; pa3 = a1p1[k0 + acol + 4];
        }
    };

    {
        loadA(0);
        const float* bp = B;
#pragma unroll
        for (int i = 0; i < NBL; i++) pb[i] = bp[b_goff[i]];
        unsigned* aw = &As[0][t * 4];
        aw[0] = f2tf32(pa0); aw[1] = f2tf32(pa1);
        aw[2] = f2tf32(pa2); aw[3] = f2tf32(pa3);
#pragma unroll
        for (int i = 0; i < NBL; i++) Bs[0][b_soff[i]] = f2tf32(pb[i]);
    }
    __syncthreads();

    for (int c = 0; c < nchunks; c++) {
        const int s = c & 1;
        const bool more = (c + 1 < nchunks);
        if (more) {
            int k0 = (c + 1) << 4;
            loadA(k0);
            const float* bp = B + (size_t)k0 * N;
#pragma unroll
            for (int i = 0; i < NBL; i++) pb[i] = bp[b_goff[i]];
        }

#pragma unroll
        for (int kf = 0; kf < 2; kf++) {
            uint4 afr[2];
            afr[0] = *(const uint4*)&As[s][(((wm * 2 + 0) * 2 + kf) * 32 + lane) * 4];
            afr[1] = *(const uint4*)&As[s][(((wm * 2 + 1) * 2 + kf) * 32 + lane) * 4];
#pragma unroll
            for (int nf = 0; nf < NF; nf++) {
                int cb = wn * (BN / 4) + nf * 8 + gid;
                unsigned bb0 = Bs[s][(kf * 8 + tig) * BSST + cb];
                unsigned bb1 = Bs[s][(kf * 8 + tig + 4) * BSST + cb];
                mma_tf32(accd[0][nf], afr[0], bb0, bb1);
                mma_tf32(accd[1][nf], afr[1], bb0, bb1);
            }
        }

        if (more) {
            const int s2 = s ^ 1;
            unsigned* aw = &As[s2][t * 4];
            aw[0] = f2tf32(pa0); aw[1] = f2tf32(pa1);
            aw[2] = f2tf32(pa2); aw[3] = f2tf32(pa3);
#pragma unroll
            for (int i = 0; i < NBL; i++) Bs[s2][b_soff[i]] = f2tf32(pb[i]);
        }
        __syncthreads();
    }

#pragma unroll
    for (int mf = 0; mf < 2; mf++) {
#pragma unroll
        for (int nf = 0; nf < NF; nf++) {
            int row = bm + wm * 32 + mf * 16 + gid;
            int col = bn + wn * (BN / 4) + nf * 8 + 2 * tig;
#pragma unroll
            for (int half = 0; half < 2; half++) {
                int r = row + half * 8;
                float v0 = accd[mf][nf][half * 2 + 0];
                float v1 = accd[mf][nf][half * 2 + 1];
                size_t idx = (size_t)r * N + col;
                if (EPI == 2) {
                    v0 = gelu_tanh(v0 + bias[col]);
                    v1 = gelu_tanh(v1 + bias[col + 1]);
                } else if (EPI == 3) {
                    if (bias) { v0 += bias[col]; v1 += bias[col + 1]; }
                    v0 += res[idx]; v1 += res[idx + 1];
                } else if (EPI == 5) {
                    v0 += bias[col]     + 0.3f * pe_val(r, col,     tpos, cpos);
                    v1 += bias[col + 1] + 0.3f * pe_val(r, col + 1, tpos, cpos);
                }
                *(float2*)&C[idx] = make_float2(v0, v1);
            }
        }
    }
}

// ---------------------------------------------------------------------------
// Layer-1 dilated attention on tf32 tensor cores. One launch, grid 896,
// 128 threads (4 warps; warp w owns rows 16w..16w+15 — 64 rows total).
// bid<512: (w=64,r=1)->b1; <768: (w=128,r=2)->b2; else (w=256,r=4)->b4.
// ---------------------------------------------------------------------------
__global__ __launch_bounds__(128)
void attn_all_kernel(const float* __restrict__ q, const float* __restrict__ k,
                     const float* __restrict__ v,
                     float* __restrict__ b1, float* __restrict__ b2,
                     float* __restrict__ b4)
{
    __shared__ unsigned sh[64 * 36 * 2 + 64 * 40];   // 7168 words = 28KB
    unsigned* qs  = sh;                 // [64][36]
    unsigned* ks  = sh + 64 * 36;       // [64][36]
    unsigned* vs  = sh + 64 * 72;       // [64][40]
    unsigned* smP = sh;                 // [64][68] overlays qs+ks

    int bid = blockIdx.x;
    int r, w;
    float* buf;
    if (bid < 512)      { w = 64;  r = 1; buf = b1; }
    else if (bid < 768) { bid -= 512; w = 128; r = 2; buf = b2; }
    else                { bid -= 768; w = 256; r = 4; buf = b4; }

    const int nseg = SEQ / w;
    const int h   = bid & 7;
    const int seg = (bid >> 3) % nseg;
    const int b   = bid / (8 * nseg);
    const int base = b * SEQ + seg * w;
    const int off  = h % r;
    const int t    = threadIdx.x;
    const int lane = t & 31;
    const int wrp  = t >> 5;
    const int gid  = lane >> 2;
    const int tig  = lane & 3;

#pragma unroll
    for (int i = 0; i < 4; i++) {
        int idx = t + 128 * i;
        int j  = idx >> 3;
        int dq = (idx & 7) * 4;
        int tok = base + off + r * j;
        size_t gi = (size_t)tok * DIM + h * HDIM + dq;
        float4 qv = *(const float4*)&q[gi];
        float4 kv = *(const float4*)&k[gi];
        float4 vv = *(const float4*)&v[gi];
        uint4 qu = make_uint4(f2tf32(qv.x), f2tf32(qv.y), f2tf32(qv.z), f2tf32(qv.w));
        uint4 ku = make_uint4(f2tf32(kv.x), f2tf32(kv.y), f2tf32(kv.z), f2tf32(kv.w));
        uint4 vu = make_uint4(f2tf32(vv.x), f2tf32(vv.y), f2tf32(vv.z), f2tf32(vv.w));
        *(uint4*)&qs[j * 36 + dq] = qu;
        *(uint4*)&ks[j * 36 + dq] = ku;
        *(uint4*)&vs[j * 40 + dq] = vu;
    }
    __syncthreads();

    const int rA = wrp * 16 + gid;
    const int rB = rA + 8;
    float sacc[8][4];
#pragma unroll
    for (int nf = 0; nf < 8; nf++)
#pragma unroll
        for (int c = 0; c < 4; c++) sacc[nf][c] = 0.f;

#pragma unroll
    for (int kc = 0; kc < 4; kc++) {
        uint4 afr;
        afr.x = qs[rA * 36 + kc * 8 + tig];
        afr.y = qs[rB * 36 + kc * 8 + tig];
        afr.z = qs[rA * 36 + kc * 8 + tig + 4];
        afr.w = qs[rB * 36 + kc * 8 + tig + 4];
#pragma unroll
        for (int nf = 0; nf < 8; nf++) {
            unsigned bb0 = ks[(nf * 8 + gid) * 36 + kc * 8 + tig];
            unsigned bb1 = ks[(nf * 8 + gid) * 36 + kc * 8 + tig + 4];
            mma_tf32(sacc[nf], afr, bb0, bb1);
        }
    }

    const float scl = 0.17677669529663687f;
    float mA = -1e30f, mB = -1e30f;
#pragma unroll
    for (int nf = 0; nf < 8; nf++) {
        sacc[nf][0] *= scl; sacc[nf][1] *= scl;
        sacc[nf][2] *= scl; sacc[nf][3] *= scl;
        mA = fmaxf(mA, fmaxf(sacc[nf][0], sacc[nf][1]));
        mB = fmaxf(mB, fmaxf(sacc[nf][2], sacc[nf][3]));
    }
#pragma unroll
    for (int o = 2; o > 0; o >>= 1) {
        mA = fmaxf(mA, __shfl_xor_sync(0xffffffffu, mA, o));
        mB = fmaxf(mB, __shfl_xor_sync(0xffffffffu, mB, o));
    }
    float sA = 0.f, sB = 0.f;
#pragma unroll
    for (int nf = 0; nf < 8; nf++) {
        sacc[nf][0] = __expf(sacc[nf][0] - mA); sA += sacc[nf][0];
        sacc[nf][1] = __expf(sacc[nf][1] - mA); sA += sacc[nf][1];
        sacc[nf][2] = __expf(sacc[nf][2] - mB); sB += sacc[nf][2];
        sacc[nf][3] = __expf(sacc[nf][3] - mB); sB += sacc[nf][3];
    }
#pragma unroll
    for (int o = 2; o > 0; o >>= 1) {
        sA += __shfl_xor_sync(0xffffffffu, sA, o);
        sB += __shfl_xor_sync(0xffffffffu, sB, o);
    }
    const float iA = 1.0f / sA, iB = 1.0f / sB;

    __syncthreads();

#pragma unroll
    for (int nf = 0; nf < 8; nf++) {
        int col = nf * 8 + 2 * tig;
        uint2 pa = make_uint2(f2tf32(sacc[nf][0] * iA), f2tf32(sacc[nf][1] * iA));
        uint2 pb = make_uint2(f2tf32(sacc[nf][2] * iB), f2tf32(sacc[nf][3] * iB));
        *(uint2*)&smP[rA * 68 + col] = pa;
        *(uint2*)&smP[rB * 68 + col] = pb;
    }
    __syncthreads();

    float oacc[4][4];
#pragma unroll
    for (int nf = 0; nf < 4; nf++)
#pragma unroll
        for (int c = 0; c < 4; c++) oacc[nf][c] = 0.f;

#pragma unroll
    for (int kc = 0; kc < 8; kc++) {
        uint4 afr;
        afr.x = smP[rA * 68 + kc * 8 + tig];
        afr.y = smP[rB * 68 + kc * 8 + tig];
        afr.z = smP[rA * 68 + kc * 8 + tig + 4];
        afr.w = smP[rB * 68 + kc * 8 + tig + 4];
#pragma unroll
        for (int nf = 0; nf < 4; nf++) {
            unsigned bb0 = vs[(kc * 8 + tig) * 40 + nf * 8 + gid];
            unsigned bb1 = vs[(kc * 8 + tig + 4) * 40 + nf * 8 + gid];
            mma_tf32(oacc[nf], afr, bb0, bb1);
        }
    }

    const float third = 1.0f / 3.0f;
    const int tokA = base + off + r * rA;
    const int tokB = base + off + r * rB;
#pragma unroll
    for (int nf = 0; nf < 4; nf++) {
        int col = h * HDIM + nf * 8 + 2 * tig;
        *(float2*)&buf[(size_t)tokA * DIM + col] =
            make_float2(oacc[nf][0] * third, oacc[nf][1] * third);
        *(float2*)&buf[(size_t)tokB * DIM + col] =
            make_float2(oacc[nf][2] * third, oacc[nf][3] * third);
    }
}

// ---------------------------------------------------------------------------
// Layer-2 fused tail (per batch): LN1 (token0), q gemv, token-0 attn,
// Wo+res, LN2, FFN, LNf.
// ---------------------------------------------------------------------------
__global__ __launch_bounds__(256)
void tail_kernel(const float* __restrict__ x,
                 const float* __restrict__ k,  const float* __restrict__ v,
                 const float* __restrict__ Wq, const float* __restrict__ Wo,
                 const float* __restrict__ W1, const float* __restrict__ W2,
                 const float* __restrict__ b1v, const float* __restrict__ b2v,
                 const float* __restrict__ ln1s, const float* __restrict__ ln1b,
                 const float* __restrict__ ln2s, const float* __restrict__ ln2b,
                 const float* __restrict__ lnfs, const float* __restrict__ lnfb,
                 float* __restrict__ out)
{
    __shared__ float xs[256], hq[256], qsh[256], att[256], x1[256], h2[256];
    __shared__ float f[1024];
    __shared__ float red[4 * 256];
    __shared__ float psh[8][64];
    __shared__ float rsum[8];

    const int b    = blockIdx.x;
    const int t    = threadIdx.x;
    const int lane = t & 31;
    const int wrp  = t >> 5;
    const size_t row0 = (size_t)b * SEQ * DIM;

    xs[t] = x[row0 + t];
    __syncthreads();

    // ---- hq = LN1(xs) ----
    {
        float val = xs[t];
        float s = wred_sum(val);
        if (lane == 0) rsum[wrp] = s;
        __syncthreads();
        float tot = 0.f;
#pragma unroll
        for (int i = 0; i < 8; i++) tot += rsum[i];
        float mu = tot * (1.0f / 256.0f);
        __syncthreads();
        float dv = val - mu;
        float s2 = wred_sum(dv * dv);
        if (lane == 0) rsum[wrp] = s2;
        __syncthreads();
        float tv = 0.f;
#pragma unroll
        for (int i = 0; i < 8; i++) tv += rsum[i];
        float inv = rsqrtf(tv * (1.0f / 256.0f) + 1e-5f);
        hq[t] = dv * inv * ln1s[t] + ln1b[t];
        __syncthreads();
    }

    // ---- q = hq @ Wq (split-K x4) ----
    {
        const int c4 = (t & 63) * 4;
        const int ks = t >> 6;
        float4 a = make_float4(0.f, 0.f, 0.f, 0.f);
        for (int kk = 0; kk < 64; kk++) {
            int ki = ks * 64 + kk;
            float s = hq[ki];
            float4 w = *(const float4*)&Wq[(size_t)ki * 256 + c4];
            a.x += s * w.x; a.y += s * w.y; a.z += s * w.z; a.w += s * w.w;
        }
        *(float4*)&red[ks * 256 + c4] = a;
        __syncthreads();
        qsh[t] = red[t] + red[256 + t] + red[512 + t] + red[768 + t];
        __syncthreads();
    }

    // ---- token-0 dilated attention ----
    {
        const int h = wrp;
        float o = 0.f;
        const float4* qv = (const float4*)&qsh[h * 32];
#pragma unroll
        for (int c = 0; c < 3; c++) {
            const int r = 1 << c;
            if (h % r == 0) {
                const float4* k0p = (const float4*)(k + ((size_t)(b * 256 + r * lane) * DIM) + h * 32);
                const float4* k1p = (const float4*)(k + ((size_t)(b * 256 + r * (lane + 32)) * DIM) + h * 32);
                float s0 = 0.f, s1 = 0.f;
#pragma unroll
                for (int u = 0; u < 8; u++) {
                    float4 qd = qv[u];
                    float4 ka = k0p[u];
                    float4 kb = k1p[u];
                    s0 += qd.x * ka.x + qd.y * ka.y + qd.z * ka.z + qd.w * ka.w;
                    s1 += qd.x * kb.x + qd.y * kb.y + qd.z * kb.z + qd.w * kb.w;
                }
                s0 *= 0.17677669529663687f;
                s1 *= 0.17677669529663687f;
                float mx = fmaxf(s0, s1);
#pragma unroll
                for (int ofs = 16; ofs > 0; ofs >>= 1)
                    mx = fmaxf(mx, __shfl_xor_sync(0xffffffffu, mx, ofs));
                float e0 = __expf(s0 - mx), e1 = __expf(s1 - mx);
                float sm = wred_sum(e0 + e1);
                float inv = 1.0f / sm;
                psh[h][lane]      = e0 * inv;
                psh[h][lane + 32] = e1 * inv;
                __syncwarp();
                float oc = 0.f;
#pragma unroll 8
                for (int j = 0; j < 64; j++)
                    oc += psh[h][j] * v[((size_t)(b * 256 + r * j) * DIM) + h * 32 + lane];
                o += oc;
                __syncwarp();
            }
        }
        att[h * 32 + lane] = o * (1.0f / 3.0f);
    }
    __syncthreads();

    // ---- x1 = att @ Wo + xs ----
    {
        const int c4 = (t & 63) * 4;
        const int ks = t >> 6;
        float4 a = make_float4(0.f, 0.f, 0.f, 0.f);
        for (int kk = 0; kk < 64; kk++) {
            int ki = ks * 64 + kk;
            float s = att[ki];
            float4 w = *(const float4*)&Wo[(size_t)ki * 256 + c4];
            a.x += s * w.x; a.y += s * w.y; a.z += s * w.z; a.w += s * w.w;
        }
        __syncthreads();
        *(float4*)&red[ks * 256 + c4] = a;
        __syncthreads();
        x1[t] = red[t] + red[256 + t] + red[512 + t] + red[768 + t] + xs[t];
        __syncthreads();
    }

    // ---- h2 = LN2(x1) ----
    {
        float val = x1[t];
        float s = wred_sum(val);
        if (lane == 0) rsum[wrp] = s;
        __syncthreads();
        float tot = 0.f;
#pragma unroll
        for (int i = 0; i < 8; i++) tot += rsum[i];
        float mu = tot * (1.0f / 256.0f);
        __syncthreads();
        float dv = val - mu;
        float s2 = wred_sum(dv * dv);
        if (lane == 0) rsum[wrp] = s2;
        __syncthreads();
        float tv = 0.f;
#pragma unroll
        for (int i = 0; i < 8; i++) tv += rsum[i];
        float inv = rsqrtf(tv * (1.0f / 256.0f) + 1e-5f);
        h2[t] = dv * inv * ln2s[t] + ln2b[t];
        __syncthreads();
    }

    // ---- f = gelu(h2 @ W1 + b1) ----
    {
        const int c4 = t * 4;
        float4 a = make_float4(0.f, 0.f, 0.f, 0.f);
        for (int ki = 0; ki < 256; ki++) {
            float s = h2[ki];
            float4 w = *(const float4*)&W1[(size_t)ki * 1024 + c4];
            a.x += s * w.x; a.y += s * w.y; a.z += s * w.z; a.w += s * w.w;
        }
        float4 bb = *(const float4*)&b1v[c4];
        f[c4 + 0] = gelu_tanh(a.x + bb.x);
        f[c4 + 1] = gelu_tanh(a.y + bb.y);
        f[c4 + 2] = gelu_tanh(a.z + bb.z);
        f[c4 + 3] = gelu_tanh(a.w + bb.w);
        __syncthreads();
    }

    // ---- y = f @ W2 + b2 + x1 ; out = LNf(y) ----
    {
        const int c4 = (t & 63) * 4;
        const int ks = t >> 6;
        float4 a = make_float4(0.f, 0.f, 0.f, 0.f);
        for (int kk = 0; kk < 256; kk++) {
            int ki = ks * 256 + kk;
            float s = f[ki];
            float4 w = *(const float4*)&W2[(size_t)ki * 256 + c4];
            a.x += s * w.x; a.y += s * w.y; a.z += s * w.z; a.w += s * w.w;
        }
        *(float4*)&red[ks * 256 + c4] = a;
        __syncthreads();
        float y = red[t] + red[256 + t] + red[512 + t] + red[768 + t] + b2v[t] + x1[t];

        float s = wred_sum(y);
        if (lane == 0) rsum[wrp] = s;
        __syncthreads();
        float tot = 0.f;
#pragma unroll
        for (int i = 0; i < 8; i++) tot += rsum[i];
        float mu = tot * (1.0f / 256.0f);
        __syncthreads();
        float dv = y - mu;
        float s2 = wred_sum(dv * dv);
        if (lane == 0) rsum[wrp] = s2;
        __syncthreads();
        float tv = 0.f;
#pragma unroll
        for (int i = 0; i < 8; i++) tv += rsum[i];
        float inv = rsqrtf(tv * (1.0f / 256.0f) + 1e-5f);
        out[(size_t)b * 256 + t] = dv * inv * lnfs[t] + lnfb[t];
    }
}

// ---------------------------------------------------------------------------
// Orchestration: 8 launches total.
// ---------------------------------------------------------------------------
extern "C" void kernel_launch(void* const* d_in, const int* in_sizes, int n_in,
                              void* d_out, int out_size)
{
    const float* target_feat   = (const float*)d_in[0];
    const float* context_feats = (const float*)d_in[1];
    const float* target_pos    = (const float*)d_in[2];
    const float* context_pos   = (const float*)d_in[3];
    const float* W_proj        = (const float*)d_in[4];
    const float* b_proj        = (const float*)d_in[5];
    const float* Wq            = (const float*)d_in[6];
    const float* Wk            = (const float*)d_in[7];
    const float* Wv            = (const float*)d_in[8];
    const float* Wo            = (const float*)d_in[9];
    const float* ln1_s         = (const float*)d_in[10];
    const float* ln1_b         = (const float*)d_in[11];
    const float* ln2_s         = (const float*)d_in[12];
    const float* ln2_b         = (const float*)d_in[13];
    const float* W1            = (const float*)d_in[14];
    const float* b1            = (const float*)d_in[15];
    const float* W2            = (const float*)d_in[16];
    const float* b2            = (const float*)d_in[17];
    const float* lnf_s         = (const float*)d_in[18];
    const float* lnf_b         = (const float*)d_in[19];
    float* out = (float*)d_out;

    float *x, *h, *q, *k, *v, *accb, *ffn;
    cudaGetSymbolAddress((void**)&x,    g_x);
    cudaGetSymbolAddress((void**)&h,    g_h);
    cudaGetSymbolAddress((void**)&q,    g_q);
    cudaGetSymbolAddress((void**)&k,    g_k);
    cudaGetSymbolAddress((void**)&v,    g_v);
    cudaGetSymbolAddress((void**)&accb, g_acc);
    cudaGetSymbolAddress((void**)&ffn,  g_ffn);

    const dim3 blk(256);
    const dim3 gN128 (DIM / 128, TOK / 64, 1);       // (2, 64)
    const dim3 gQKV  (DIM / 128, TOK / 64, 3);       // (2, 64, 3)
    const dim3 gKV   (DIM / 128, TOK / 64, 2);       // (2, 64, 2)
    const dim3 gFFN1 (FFN_DIM / 128, TOK / 64, 1);   // (8, 64)

    // 1. Projection (+bias +posenc fused), K=512
    mma_gemm<5, 128, true, false, false><<<gN128, blk>>>(
        nullptr, nullptr, nullptr, W_proj, nullptr, nullptr,
        b_proj, nullptr, x, nullptr, nullptr, DIM, INDIM,
        target_feat, context_feats, target_pos, context_pos,
        nullptr, nullptr);

    // ======================= Layer 1 (full) =======================
    // 2. QKV fused, LN1 fused into A-prologue
    mma_gemm<0, 128, false, false, true><<<gQKV, blk>>>(
        x, nullptr, nullptr, Wq, Wk, Wv,
        nullptr, nullptr, q, k, v, DIM, DIM,
        nullptr, nullptr, nullptr, nullptr,
        ln1_s, ln1_b);

    // 3. Attention (all configs, disjoint buffers)
    attn_all_kernel<<<896, 128>>>(q, k, v, accb, h, ffn);

    // 4. Wo with masked 3-buffer A-sum + residual
    mma_gemm<3, 128, false, true, false><<<gN128, blk>>>(
        accb, h, ffn, Wo, nullptr, nullptr,
        nullptr, x, x, nullptr, nullptr, DIM, DIM,
        nullptr, nullptr, nullptr, nullptr,
        nullptr, nullptr);

    // 5. FFN1: ffn = gelu(LN2(x) @ W1 + b1), LN fused
    mma_gemm<2, 128, false, false, true><<<gFFN1, blk>>>(
        x, nullptr, nullptr, W1, nullptr, nullptr,
        b1, nullptr, ffn, nullptr, nullptr, FFN_DIM, DIM,
        nullptr, nullptr, nullptr, nullptr,
        ln2_s, ln2_b);

    // 6. FFN2: x = ffn @ W2 + b2 + x
    mma_gemm<3, 128, false, false, false><<<gN128, blk>>>(
        ffn, nullptr, nullptr, W2, nullptr, nullptr,
        b2, x, x, nullptr, nullptr, DIM, FFN_DIM,
        nullptr, nullptr, nullptr, nullptr,
        nullptr, nullptr);

    // ================== Layer 2 (token-0 truncated) ==================
    // 7. K,V full, LN1(l2) fused
    mma_gemm<0, 128, false, false, true><<<gKV, blk>>>(
        x, nullptr, nullptr, Wk + DIM * DIM, Wv + DIM * DIM, nullptr,
        nullptr, nullptr, k, v, nullptr, DIM, DIM,
        nullptr, nullptr, nullptr, nullptr,
        ln1_s + DIM, ln1_b + DIM);

    // 8. Fused tail: LN1(tok0), q gemv, attn, Wo+res, LN2, FFN, LNf -> out
    tail_kernel<<<BATCH, blk>>>(
        x, k, v,
        Wq + DIM * DIM, Wo + DIM * DIM,
        W1 + DIM * FFN_DIM, W2 + FFN_DIM * DIM,
        b1 + FFN_DIM, b2 + DIM,
        ln1_s + DIM, ln1_b + DIM,
        ln2_s + DIM, ln2_b + DIM, lnf_s, lnf_b, out);
}

// round 11
// speedup vs baseline: 1.2902x; 1.2902x over previous
#include <cuda_runtime.h>
#include <math.h>

// ---------------------------------------------------------------------------
// GlobalLocalAwareEncoder — truncated-dependency implementation.
// T1: dilated segments never cross 256-token boundaries -> token 0 depends
//     only on tokens [0,256) per batch.
// T2: layer 2 is last -> only token 0 per batch feeds output (fused tail).
// Attention: tf32 m16n8k8, one launch, 3 disjoint buffers; Wo sums w/ masks.
// Plain GEMMs (QKV/FFN1/FFN2/KV): cp.async 3-stage pipelined tf32 MMA.
// proj (gather+posenc) and Wo (3-buffer sum) keep the register-prefetch GEMM.
// ---------------------------------------------------------------------------

#define BATCH   16
#define SEQ     256
#define TOK     (BATCH * SEQ)   // 4096
#define DIM     256
#define HEADS   8
#define HDIM    32
#define FFN_DIM 1024
#define INDIM   512
#define NCTX    4095

__device__ float g_x  [TOK * DIM];
__device__ float g_h  [TOK * DIM];     // LN output + attention b2 scratch
__device__ float g_q  [TOK * DIM];
__device__ float g_k  [TOK * DIM];
__device__ float g_v  [TOK * DIM];
__device__ float g_acc[TOK * DIM];     // attention b1 scratch
__device__ float g_ffn[TOK * FFN_DIM]; // attention b4 scratch + FFN hidden

__device__ __forceinline__ float gelu_tanh(float x) {
    float x3 = x * x * x;
    return 0.5f * x * (1.0f + tanhf(0.7978845608028654f * (x + 0.044715f * x3)));
}

__device__ __forceinline__ unsigned f2tf32(float f) {
    unsigned u;
    asm("cvt.rna.tf32.f32 %0, %1;" : "=r"(u) : "f"(f));
    return u;
}

__device__ __forceinline__ void mma_tf32(float* d, uint4 a, unsigned b0, unsigned b1) {
    asm volatile(
        "mma.sync.aligned.m16n8k8.row.col.f32.tf32.tf32.f32 "
        "{%0,%1,%2,%3}, {%4,%5,%6,%7}, {%8,%9}, {%0,%1,%2,%3};"
        : "+f"(d[0]), "+f"(d[1]), "+f"(d[2]), "+f"(d[3])
        : "r"(a.x), "r"(a.y), "r"(a.z), "r"(a.w), "r"(b0), "r"(b1));
}

__device__ __forceinline__ void cpa16(unsigned dst, const float* src) {
    asm volatile("cp.async.cg.shared.global [%0], [%1], 16;" :: "r"(dst), "l"(src));
}

__device__ __forceinline__ float wred_sum(float v) {
#pragma unroll
    for (int o = 16; o > 0; o >>= 1) v += __shfl_xor_sync(0xffffffffu, v, o);
    return v;
}

// positional encoding value for (token row, channel col), dim=256
__device__ __forceinline__ float pe_val(int row, int col,
                                        const float* __restrict__ tpos,
                                        const float* __restrict__ cpos) {
    int b = row >> 8, s = row & 255;
    const float* pp = (s == 0) ? (tpos + (size_t)b * 2)
                               : (cpos + ((size_t)b * NCTX + (s - 1)) * 2);
    float pos = (col < 128) ? pp[0] : pp[1];
    int dd = col & 127;
    int i  = dd & 63;
    float omega = expf(-(float)i * (9.210340371976184f / 64.0f));
    float ang = pos * omega;
    return (dd < 64) ? sinf(ang) : cosf(ang);
}

// ---------------------------------------------------------------------------
// Pipelined tf32 GEMM (plain A). C[4096,N] = A[4096,K] @ B[K,N].
// BM=64, BN=128, BK=16, 3-stage cp.async ring, 256 threads (8 warps, 32x32).
// Raw fp32 bits fed to mma.tf32 (implicit truncation; no cvt).
// EPI: 0 store / 2 gelu(v+bias) / 3 v+res+bias. blockIdx.z selects B/C.
// ---------------------------------------------------------------------------
#define PAS 1280   // 64 * 20 words per A stage
#define PBS 2176   // 16 * 136 words per B stage

template<int EPI>
__global__ __launch_bounds__(256)
void gemm_pipe(const float* __restrict__ A,
               const float* __restrict__ B0, const float* __restrict__ B1,
               const float* __restrict__ B2,
               const float* __restrict__ bias, const float* __restrict__ res,
               float* __restrict__ C0, float* __restrict__ C1, float* __restrict__ C2,
               int N, int K)
{
    __shared__ float sm[3 * (PAS + PBS)];   // 41472 B
    float* AsB = sm;
    float* BsB = sm + 3 * PAS;

    const int z = blockIdx.z;
    const float* B = (z == 0) ? B0 : (z == 1) ? B1 : B2;
    float*       C = (z == 0) ? C0 : (z == 1) ? C1 : C2;

    const int t    = threadIdx.x;
    const int lane = t & 31;
    const int warp = t >> 5;
    const int wm   = warp >> 2;
    const int wn   = warp & 3;
    const int gid  = lane >> 2;
    const int tig  = lane & 3;

    const int bm = blockIdx.y * 64;
    const int bn = blockIdx.x * 128;

    // ---- cp.async source/dest mapping ----
    const int arow = t >> 2;            // 0..63
    const int akq  = (t & 3) * 4;       // 0,4,8,12
    const float* aptr = A + (size_t)(bm + arow) * K + akq;
    const unsigned a_dst = (unsigned)__cvta_generic_to_shared(AsB + arow * 20 + akq);

    const int kr0 = t >> 5;             // 0..7
    const int nq  = (t & 31) * 4;       // 0..124
    const float* bptr0 = B + (size_t)kr0 * N + bn + nq;
    const float* bptr1 = B + (size_t)(kr0 + 8) * N + bn + nq;
    const unsigned b_dst0 = (unsigned)__cvta_generic_to_shared(BsB + kr0 * 136 + nq);
    const unsigned b_dst1 = (unsigned)__cvta_generic_to_shared(BsB + (kr0 + 8) * 136 + nq);

    const int nchunks = K >> 4;

    auto issue = [&](int c) {
        if (c < nchunks) {
            int st = c % 3;
            cpa16(a_dst  + st * PAS * 4, aptr  + c * 16);
            cpa16(b_dst0 + st * PBS * 4, bptr0 + (size_t)c * 16 * N);
            cpa16(b_dst1 + st * PBS * 4, bptr1 + (size_t)c * 16 * N);
        }
        asm volatile("cp.async.commit_group;");
    };

    float accd[2][4][4];
#pragma unroll
    for (int mf = 0; mf < 2; mf++)
#pragma unroll
        for (int nf = 0; nf < 4; nf++)
#pragma unroll
            for (int r = 0; r < 4; r++) accd[mf][nf][r] = 0.f;

    issue(0);
    issue(1);

    for (int c = 0; c < nchunks; c++) {
        asm volatile("cp.async.wait_group 1;");
        __syncthreads();
        issue(c + 2);

        const int st = c % 3;
        const float* Asp = AsB + st * PAS;
        const float* Bsp = BsB + st * PBS;
#pragma unroll
        for (int kf = 0; kf < 2; kf++) {
            uint4 afr[2];
#pragma unroll
            for (int mf = 0; mf < 2; mf++) {
                int rb = wm * 32 + mf * 16;
                afr[mf].x = __float_as_uint(Asp[(rb + gid)     * 20 + kf * 8 + tig]);
                afr[mf].y = __float_as_uint(Asp[(rb + 8 + gid) * 20 + kf * 8 + tig]);
                afr[mf].z = __float_as_uint(Asp[(rb + gid)     * 20 + kf * 8 + tig + 4]);
                afr[mf].w = __float_as_uint(Asp[(rb + 8 + gid) * 20 + kf * 8 + tig + 4]);
            }
#pragma unroll
            for (int nf = 0; nf < 4; nf++) {
                int cb = wn * 32 + nf * 8 + gid;
                unsigned bb0 = __float_as_uint(Bsp[(kf * 8 + tig)     * 136 + cb]);
                unsigned bb1 = __float_as_uint(Bsp[(kf * 8 + tig + 4) * 136 + cb]);
                mma_tf32(accd[0][nf], afr[0], bb0, bb1);
                mma_tf32(accd[1][nf], afr[1], bb0, bb1);
            }
        }
    }

    // ---- epilogue ----
#pragma unroll
    for (int mf = 0; mf < 2; mf++) {
#pragma unroll
        for (int nf = 0; nf < 4; nf++) {
            int row = bm + wm * 32 + mf * 16 + gid;
            int col = bn + wn * 32 + nf * 8 + 2 * tig;
#pragma unroll
            for (int half = 0; half < 2; half++) {
                int r = row + half * 8;
                float v0 = accd[mf][nf][half * 2 + 0];
                float v1 = accd[mf][nf][half * 2 + 1];
                size_t idx = (size_t)r * N + col;
                if (EPI == 2) {
                    v0 = gelu_tanh(v0 + bias[col]);
                    v1 = gelu_tanh(v1 + bias[col + 1]);
                } else if (EPI == 3) {
                    if (bias) { v0 += bias[col]; v1 += bias[col + 1]; }
                    v0 += res[idx]; v1 += res[idx + 1];
                }
                *(float2*)&C[idx] = make_float2(v0, v1);
            }
        }
    }
}

// ---------------------------------------------------------------------------
// Register-prefetch tf32 GEMM (special A paths: GATHER / ASUM3). As in R8.
// EPI: 3 v+res(+bias) / 5 v+bias+0.3*posenc
// ---------------------------------------------------------------------------
template<int EPI, bool GATHER, bool ASUM3>
__global__ __launch_bounds__(256)
void mma_gemm(const float* __restrict__ A,
              const float* __restrict__ A2, const float* __restrict__ A4,
              const float* __restrict__ B0,
              const float* __restrict__ bias, const float* __restrict__ res,
              float* __restrict__ C0,
              int N, int K,
              const float* __restrict__ tfeat, const float* __restrict__ cfeat,
              const float* __restrict__ tpos,  const float* __restrict__ cpos)
{
    constexpr int BN = 128;
    constexpr int BSST = BN + 8;
    constexpr int NF   = BN / 32;
    constexpr int NBL  = BN / 16;

    __shared__ unsigned As[2][1024];
    __shared__ unsigned Bs[2][16 * BSST];

    const float* B = B0;
    float*       C = C0;

    const int t    = threadIdx.x;
    const int lane = t & 31;
    const int warp = t >> 5;
    const int wm   = warp >> 2;
    const int wn   = warp & 3;
    const int gid  = lane >> 2;
    const int tig  = lane & 3;

    const int bm = blockIdx.y * 64;
    const int bn = blockIdx.x * BN;

    const int a_mf = t >> 6;
    const int al   = t & 31;
    const int arow = a_mf * 16 + (al >> 2);
    const int acol = ((t >> 5) & 1) * 8 + (al & 3);

    const int r0row = bm + arow;
    const int r1row = r0row + 8;

    const float *a1p0, *a1p1;
    const float *a2p0 = nullptr, *a2p1 = nullptr, *a4p0 = nullptr, *a4p1 = nullptr;
    if (GATHER) {
        int b0i = r0row >> 8, s0 = r0row & 255;
        int b1i = r1row >> 8, s1 = r1row & 255;
        a1p0 = (s0 == 0) ? (tfeat + (size_t)b0i * INDIM)
                         : (cfeat + ((size_t)b0i * NCTX + (s0 - 1)) * INDIM);
        a1p1 = (s1 == 0) ? (tfeat + (size_t)b1i * INDIM)
                         : (cfeat + ((size_t)b1i * NCTX + (s1 - 1)) * INDIM);
    } else {
        a1p0 = A + (size_t)r0row * K;
        a1p1 = A + (size_t)r1row * K;
        if (ASUM3) {
            a2p0 = A2 + (size_t)r0row * K;  a2p1 = A2 + (size_t)r1row * K;
            a4p0 = A4 + (size_t)r0row * K;  a4p1 = A4 + (size_t)r1row * K;
        }
    }

    int b_goff[NBL], b_soff[NBL];
#pragma unroll
    for (int i = 0; i < NBL; i++) {
        int idx = t + 256 * i;
        int kk  = idx / BN;
        int n   = idx % BN;
        b_goff[i] = kk * N + bn + n;
        b_soff[i] = kk * BSST + n;
    }

    float accd[2][NF][4];
#pragma unroll
    for (int mf = 0; mf < 2; mf++)
#pragma unroll
        for (int nf = 0; nf < NF; nf++)
#pragma unroll
            for (int r = 0; r < 4; r++) accd[mf][nf][r] = 0.f;

    const int nchunks = K >> 4;
    float pa0, pa1, pa2, pa3;
    float pb[NBL];

    auto loadA = [&](int k0) {
        if (ASUM3) {
            int kc  = k0 + acol;
            int hh  = kc >> 5;
            bool m20 = ((r0row ^ hh) & 1) == 0, m40 = ((r0row ^ hh) & 3) == 0;
            bool m21 = ((r1row ^ hh) & 1) == 0, m41 = ((r1row ^ hh) & 3) == 0;
            pa0 = a1p0[kc]     + (m20 ? a2p0[kc]     : 0.f) + (m40 ? a4p0[kc]     : 0.f);
            pa1 = a1p1[kc]     + (m21 ? a2p1[kc]     : 0.f) + (m41 ? a4p1[kc]     : 0.f);
            pa2 = a1p0[kc + 4] + (m20 ? a2p0[kc + 4] : 0.f) + (m40 ? a4p0[kc + 4] : 0.f);
            pa3 = a1p1[kc + 4] + (m21 ? a2p1[kc + 4] : 0.f) + (m41 ? a4p1[kc + 4] : 0.f);
        } else {
            pa0 = a1p0[k0 + acol];     pa1 = a1p1[k0 + acol];
            pa2 = a1p0[k0 + acol + 4]; pa3 = a1p1[k0 + acol + 4];
        }
    };

    {
        loadA(0);
        const float* bp = B;
#pragma unroll
        for (int i = 0; i < NBL; i++) pb[i] = bp[b_goff[i]];
        unsigned* aw = &As[0][t * 4];
        aw[0] = f2tf32(pa0); aw[1] = f2tf32(pa1);
        aw[2] = f2tf32(pa2); aw[3] = f2tf32(pa3);
#pragma unroll
        for (int i = 0; i < NBL; i++) Bs[0][b_soff[i]] = f2tf32(pb[i]);
    }
    __syncthreads();

    for (int c = 0; c < nchunks; c++) {
        const int s = c & 1;
        const bool more = (c + 1 < nchunks);
        if (more) {
            int k0 = (c + 1) << 4;
            loadA(k0);
            const float* bp = B + (size_t)k0 * N;
#pragma unroll
            for (int i = 0; i < NBL; i++) pb[i] = bp[b_goff[i]];
        }

#pragma unroll
        for (int kf = 0; kf < 2; kf++) {
            uint4 afr[2];
            afr[0] = *(const uint4*)&As[s][(((wm * 2 + 0) * 2 + kf) * 32 + lane) * 4];
            afr[1] = *(const uint4*)&As[s][(((wm * 2 + 1) * 2 + kf) * 32 + lane) * 4];
#pragma unroll
            for (int nf = 0; nf < NF; nf++) {
                int cb = wn * (BN / 4) + nf * 8 + gid;
                unsigned bb0 = Bs[s][(kf * 8 + tig) * BSST + cb];
                unsigned bb1 = Bs[s][(kf * 8 + tig + 4) * BSST + cb];
                mma_tf32(accd[0][nf], afr[0], bb0, bb1);
                mma_tf32(accd[1][nf], afr[1], bb0, bb1);
            }
        }

        if (more) {
            const int s2 = s ^ 1;
            unsigned* aw = &As[s2][t * 4];
            aw[0] = f2tf32(pa0); aw[1] = f2tf32(pa1);
            aw[2] = f2tf32(pa2); aw[3] = f2tf32(pa3);
#pragma unroll
            for (int i = 0; i < NBL; i++) Bs[s2][b_soff[i]] = f2tf32(pb[i]);
        }
        __syncthreads();
    }

#pragma unroll
    for (int mf = 0; mf < 2; mf++) {
#pragma unroll
        for (int nf = 0; nf < NF; nf++) {
            int row = bm + wm * 32 + mf * 16 + gid;
            int col = bn + wn * (BN / 4) + nf * 8 + 2 * tig;
#pragma unroll
            for (int half = 0; half < 2; half++) {
                int r = row + half * 8;
                float v0 = accd[mf][nf][half * 2 + 0];
                float v1 = accd[mf][nf][half * 2 + 1];
                size_t idx = (size_t)r * N + col;
                if (EPI == 3) {
                    if (bias) { v0 += bias[col]; v1 += bias[col + 1]; }
                    v0 += res[idx]; v1 += res[idx + 1];
                } else if (EPI == 5) {
                    v0 += bias[col]     + 0.3f * pe_val(r, col,     tpos, cpos);
                    v1 += bias[col + 1] + 0.3f * pe_val(r, col + 1, tpos, cpos);
                }
                *(float2*)&C[idx] = make_float2(v0, v1);
            }
        }
    }
}

// ---------------------------------------------------------------------------
// LayerNorm: one warp per token, D=256.
// ---------------------------------------------------------------------------
__global__ void ln_kernel(const float* __restrict__ x, const float* __restrict__ sc,
                          const float* __restrict__ bi, float* __restrict__ out,
                          int ntok, int in_stride)
{
    int gw   = (blockIdx.x * blockDim.x + threadIdx.x) >> 5;
    int lane = threadIdx.x & 31;
    if (gw >= ntok) return;
    const float* xp = x + (size_t)gw * in_stride;
    float4 v0 = *(const float4*)&xp[lane * 4];
    float4 v1 = *(const float4*)&xp[128 + lane * 4];
    float va[8] = {v0.x, v0.y, v0.z, v0.w, v1.x, v1.y, v1.z, v1.w};

    float s = 0.f;
#pragma unroll
    for (int c = 0; c < 8; c++) s += va[c];
    s = wred_sum(s);
    float mu = s * (1.0f / 256.0f);

    float ss = 0.f;
#pragma unroll
    for (int c = 0; c < 8; c++) { float d = va[c] - mu; ss += d * d; }
    ss = wred_sum(ss);
    float inv = rsqrtf(ss * (1.0f / 256.0f) + 1e-5f);

    float ovals[8];
#pragma unroll
    for (int c = 0; c < 8; c++) {
        int d = (c < 4) ? (lane * 4 + c) : (128 + lane * 4 + (c - 4));
        ovals[c] = (va[c] - mu) * inv * sc[d] + bi[d];
    }
    float* op = out + (size_t)gw * 256;
    *(float4*)&op[lane * 4]       = make_float4(ovals[0], ovals[1], ovals[2], ovals[3]);
    *(float4*)&op[128 + lane * 4] = make_float4(ovals[4], ovals[5], ovals[6], ovals[7]);
}

// ---------------------------------------------------------------------------
// Layer-1 dilated attention on tf32 tensor cores (grid 896, 128 threads).
// ---------------------------------------------------------------------------
__global__ __launch_bounds__(128)
void attn_all_kernel(const float* __restrict__ q, const float* __restrict__ k,
                     const float* __restrict__ v,
                     float* __restrict__ b1, float* __restrict__ b2,
                     float* __restrict__ b4)
{
    __shared__ unsigned sh[64 * 36 * 2 + 64 * 40];
    unsigned* qs  = sh;
    unsigned* ks  = sh + 64 * 36;
    unsigned* vs  = sh + 64 * 72;
    unsigned* smP = sh;

    int bid = blockIdx.x;
    int r, w;
    float* buf;
    if (bid < 512)      { w = 64;  r = 1; buf = b1; }
    else if (bid < 768) { bid -= 512; w = 128; r = 2; buf = b2; }
    else                { bid -= 768; w = 256; r = 4; buf = b4; }

    const int nseg = SEQ / w;
    const int h   = bid & 7;
    const int seg = (bid >> 3) % nseg;
    const int b   = bid / (8 * nseg);
    const int base = b * SEQ + seg * w;
    const int off  = h % r;
    const int t    = threadIdx.x;
    const int lane = t & 31;
    const int wrp  = t >> 5;
    const int gid  = lane >> 2;
    const int tig  = lane & 3;

#pragma unroll
    for (int i = 0; i < 4; i++) {
        int idx = t + 128 * i;
        int j  = idx >> 3;
        int dq = (idx & 7) * 4;
        int tok = base + off + r * j;
        size_t gi = (size_t)tok * DIM + h * HDIM + dq;
        float4 qv = *(const float4*)&q[gi];
        float4 kv = *(const float4*)&k[gi];
        float4 vv = *(const float4*)&v[gi];
        uint4 qu = make_uint4(f2tf32(qv.x), f2tf32(qv.y), f2tf32(qv.z), f2tf32(qv.w));
        uint4 ku = make_uint4(f2tf32(kv.x), f2tf32(kv.y), f2tf32(kv.z), f2tf32(kv.w));
        uint4 vu = make_uint4(f2tf32(vv.x), f2tf32(vv.y), f2tf32(vv.z), f2tf32(vv.w));
        *(uint4*)&qs[j * 36 + dq] = qu;
        *(uint4*)&ks[j * 36 + dq] = ku;
        *(uint4*)&vs[j * 40 + dq] = vu;
    }
    __syncthreads();

    const int rA = wrp * 16 + gid;
    const int rB = rA + 8;
    float sacc[8][4];
#pragma unroll
    for (int nf = 0; nf < 8; nf++)
#pragma unroll
        for (int c = 0; c < 4; c++) sacc[nf][c] = 0.f;

#pragma unroll
    for (int kc = 0; kc < 4; kc++) {
        uint4 afr;
        afr.x = qs[rA * 36 + kc * 8 + tig];
        afr.y = qs[rB * 36 + kc * 8 + tig];
        afr.z = qs[rA * 36 + kc * 8 + tig + 4];
        afr.w = qs[rB * 36 + kc * 8 + tig + 4];
#pragma unroll
        for (int nf = 0; nf < 8; nf++) {
            unsigned bb0 = ks[(nf * 8 + gid) * 36 + kc * 8 + tig];
            unsigned bb1 = ks[(nf * 8 + gid) * 36 + kc * 8 + tig + 4];
            mma_tf32(sacc[nf], afr, bb0, bb1);
        }
    }

    const float scl = 0.17677669529663687f;
    float mA = -1e30f, mB = -1e30f;
#pragma unroll
    for (int nf = 0; nf < 8; nf++) {
        sacc[nf][0] *= scl; sacc[nf][1] *= scl;
        sacc[nf][2] *= scl; sacc[nf][3] *= scl;
        mA = fmaxf(mA, fmaxf(sacc[nf][0], sacc[nf][1]));
        mB = fmaxf(mB, fmaxf(sacc[nf][2], sacc[nf][3]));
    }
#pragma unroll
    for (int o = 2; o > 0; o >>= 1) {
        mA = fmaxf(mA, __shfl_xor_sync(0xffffffffu, mA, o));
        mB = fmaxf(mB, __shfl_xor_sync(0xffffffffu, mB, o));
    }
    float sA = 0.f, sB = 0.f;
#pragma unroll
    for (int nf = 0; nf < 8; nf++) {
        sacc[nf][0] = __expf(sacc[nf][0] - mA); sA += sacc[nf][0];
        sacc[nf][1] = __expf(sacc[nf][1] - mA); sA += sacc[nf][1];
        sacc[nf][2] = __expf(sacc[nf][2] - mB); sB += sacc[nf][2];
        sacc[nf][3] = __expf(sacc[nf][3] - mB); sB += sacc[nf][3];
    }
#pragma unroll
    for (int o = 2; o > 0; o >>= 1) {
        sA += __shfl_xor_sync(0xffffffffu, sA, o);
        sB += __shfl_xor_sync(0xffffffffu, sB, o);
    }
    const float iA = 1.0f / sA, iB = 1.0f / sB;

    __syncthreads();

#pragma unroll
    for (int nf = 0; nf < 8; nf++) {
        int col = nf * 8 + 2 * tig;
        uint2 pa = make_uint2(f2tf32(sacc[nf][0] * iA), f2tf32(sacc[nf][1] * iA));
        uint2 pb = make_uint2(f2tf32(sacc[nf][2] * iB), f2tf32(sacc[nf][3] * iB));
        *(uint2*)&smP[rA * 68 + col] = pa;
        *(uint2*)&smP[rB * 68 + col] = pb;
    }
    __syncthreads();

    float oacc[4][4];
#pragma unroll
    for (int nf = 0; nf < 4; nf++)
#pragma unroll
        for (int c = 0; c < 4; c++) oacc[nf][c] = 0.f;

#pragma unroll
    for (int kc = 0; kc < 8; kc++) {
        uint4 afr;
        afr.x = smP[rA * 68 + kc * 8 + tig];
        afr.y = smP[rB * 68 + kc * 8 + tig];
        afr.z = smP[rA * 68 + kc * 8 + tig + 4];
        afr.w = smP[rB * 68 + kc * 8 + tig + 4];
#pragma unroll
        for (int nf = 0; nf < 4; nf++) {
            unsigned bb0 = vs[(kc * 8 + tig) * 40 + nf * 8 + gid];
            unsigned bb1 = vs[(kc * 8 + tig + 4) * 40 + nf * 8 + gid];
            mma_tf32(oacc[nf], afr, bb0, bb1);
        }
    }

    const float third = 1.0f / 3.0f;
    const int tokA = base + off + r * rA;
    const int tokB = base + off + r * rB;
#pragma unroll
    for (int nf = 0; nf < 4; nf++) {
        int col = h * HDIM + nf * 8 + 2 * tig;
        *(float2*)&buf[(size_t)tokA * DIM + col] =
            make_float2(oacc[nf][0] * third, oacc[nf][1] * third);
        *(float2*)&buf[(size_t)tokB * DIM + col] =
            make_float2(oacc[nf][2] * third, oacc[nf][3] * third);
    }
}

// ---------------------------------------------------------------------------
// Layer-2 fused tail (per batch): q gemv, token-0 attn, Wo+res, LN2, FFN, LNf.
// ---------------------------------------------------------------------------
__global__ __launch_bounds__(256)
void tail_kernel(const float* __restrict__ x,  const float* __restrict__ hh,
                 const float* __restrict__ k,  const float* __restrict__ v,
                 const float* __restrict__ Wq, const float* __restrict__ Wo,
                 const float* __restrict__ W1, const float* __restrict__ W2,
                 const float* __restrict__ b1v, const float* __restrict__ b2v,
                 const float* __restrict__ ln2s, const float* __restrict__ ln2b,
                 const float* __restrict__ lnfs, const float* __restrict__ lnfb,
                 float* __restrict__ out)
{
    __shared__ float xs[256], hq[256], qsh[256], att[256], x1[256], h2[256];
    __shared__ float f[1024];
    __shared__ float red[4 * 256];
    __shared__ float psh[8][64];
    __shared__ float rsum[8];

    const int b    = blockIdx.x;
    const int t    = threadIdx.x;
    const int lane = t & 31;
    const int wrp  = t >> 5;
    const size_t row0 = (size_t)b * SEQ * DIM;

    xs[t] = x[row0 + t];
    hq[t] = hh[row0 + t];
    __syncthreads();

    {
        const int c4 = (t & 63) * 4;
        const int ks = t >> 6;
        float4 a = make_float4(0.f, 0.f, 0.f, 0.f);
        for (int kk = 0; kk < 64; kk++) {
            int ki = ks * 64 + kk;
            float s = hq[ki];
            float4 w = *(const float4*)&Wq[(size_t)ki * 256 + c4];
            a.x += s * w.x; a.y += s * w.y; a.z += s * w.z; a.w += s * w.w;
        }
        *(float4*)&red[ks * 256 + c4] = a;
        __syncthreads();
        qsh[t] = red[t] + red[256 + t] + red[512 + t] + red[768 + t];
        __syncthreads();
    }

    {
        const int h = wrp;
        float o = 0.f;
        const float4* qv = (const float4*)&qsh[h * 32];
#pragma unroll
        for (int c = 0; c < 3; c++) {
            const int r = 1 << c;
            if (h % r == 0) {
                const float4* k0p = (const float4*)(k + ((size_t)(b * 256 + r * lane) * DIM) + h * 32);
                const float4* k1p = (const float4*)(k + ((size_t)(b * 256 + r * (lane + 32)) * DIM) + h * 32);
                float s0 = 0.f, s1 = 0.f;
#pragma unroll
                for (int u = 0; u < 8; u++) {
                    float4 qd = qv[u];
                    float4 ka = k0p[u];
                    float4 kb = k1p[u];
                    s0 += qd.x * ka.x + qd.y * ka.y + qd.z * ka.z + qd.w * ka.w;
                    s1 += qd.x * kb.x + qd.y * kb.y + qd.z * kb.z + qd.w * kb.w;
                }
                s0 *= 0.17677669529663687f;
                s1 *= 0.17677669529663687f;
                float mx = fmaxf(s0, s1);
#pragma unroll
                for (int ofs = 16; ofs > 0; ofs >>= 1)
                    mx = fmaxf(mx, __shfl_xor_sync(0xffffffffu, mx, ofs));
                float e0 = __expf(s0 - mx), e1 = __expf(s1 - mx);
                float sm = wred_sum(e0 + e1);
                float inv = 1.0f / sm;
                psh[h][lane]      = e0 * inv;
                psh[h][lane + 32] = e1 * inv;
                __syncwarp();
                float oc = 0.f;
#pragma unroll 8
                for (int j = 0; j < 64; j++)
                    oc += psh[h][j] * v[((size_t)(b * 256 + r * j) * DIM) + h * 32 + lane];
                o += oc;
                __syncwarp();
            }
        }
        att[h * 32 + lane] = o * (1.0f / 3.0f);
    }
    __syncthreads();

    {
        const int c4 = (t & 63) * 4;
        const int ks = t >> 6;
        float4 a = make_float4(0.f, 0.f, 0.f, 0.f);
        for (int kk = 0; kk < 64; kk++) {
            int ki = ks * 64 + kk;
            float s = att[ki];
            float4 w = *(const float4*)&Wo[(size_t)ki * 256 + c4];
            a.x += s * w.x; a.y += s * w.y; a.z += s * w.z; a.w += s * w.w;
        }
        __syncthreads();
        *(float4*)&red[ks * 256 + c4] = a;
        __syncthreads();
        x1[t] = red[t] + red[256 + t] + red[512 + t] + red[768 + t] + xs[t];
        __syncthreads();
    }

    {
        float val = x1[t];
        float s = wred_sum(val);
        if (lane == 0) rsum[wrp] = s;
        __syncthreads();
        float tot = 0.f;
#pragma unroll
        for (int i = 0; i < 8; i++) tot += rsum[i];
        float mu = tot * (1.0f / 256.0f);
        __syncthreads();
        float dv = val - mu;
        float s2 = wred_sum(dv * dv);
        if (lane == 0) rsum[wrp] = s2;
        __syncthreads();
        float tv = 0.f;
#pragma unroll
        for (int i = 0; i < 8; i++) tv += rsum[i];
        float inv = rsqrtf(tv * (1.0f / 256.0f) + 1e-5f);
        h2[t] = dv * inv * ln2s[t] + ln2b[t];
        __syncthreads();
    }

    {
        const int c4 = t * 4;
        float4 a = make_float4(0.f, 0.f, 0.f, 0.f);
        for (int ki = 0; ki < 256; ki++) {
            float s = h2[ki];
            float4 w = *(const float4*)&W1[(size_t)ki * 1024 + c4];
            a.x += s * w.x; a.y += s * w.y; a.z += s * w.z; a.w += s * w.w;
        }
        float4 bb = *(const float4*)&b1v[c4];
        f[c4 + 0] = gelu_tanh(a.x + bb.x);
        f[c4 + 1] = gelu_tanh(a.y + bb.y);
        f[c4 + 2] = gelu_tanh(a.z + bb.z);
        f[c4 + 3] = gelu_tanh(a.w + bb.w);
        __syncthreads();
    }

    {
        const int c4 = (t & 63) * 4;
        const int ks = t >> 6;
        float4 a = make_float4(0.f, 0.f, 0.f, 0.f);
        for (int kk = 0; kk < 256; kk++) {
            int ki = ks * 256 + kk;
            float s = f[ki];
            float4 w = *(const float4*)&W2[(size_t)ki * 256 + c4];
            a.x += s * w.x; a.y += s * w.y; a.z += s * w.z; a.w += s * w.w;
        }
        *(float4*)&red[ks * 256 + c4] = a;
        __syncthreads();
        float y = red[t] + red[256 + t] + red[512 + t] + red[768 + t] + b2v[t] + x1[t];

        float s = wred_sum(y);
        if (lane == 0) rsum[wrp] = s;
        __syncthreads();
        float tot = 0.f;
#pragma unroll
        for (int i = 0; i < 8; i++) tot += rsum[i];
        float mu = tot * (1.0f / 256.0f);
        __syncthreads();
        float dv = y - mu;
        float s2 = wred_sum(dv * dv);
        if (lane == 0) rsum[wrp] = s2;
        __syncthreads();
        float tv = 0.f;
#pragma unroll
        for (int i = 0; i < 8; i++) tv += rsum[i];
        float inv = rsqrtf(tv * (1.0f / 256.0f) + 1e-5f);
        out[(size_t)b * 256 + t] = dv * inv * lnfs[t] + lnfb[t];
    }
}

// ---------------------------------------------------------------------------
// Orchestration
// ---------------------------------------------------------------------------
extern "C" void kernel_launch(void* const* d_in, const int* in_sizes, int n_in,
                              void* d_out, int out_size)
{
    const float* target_feat   = (const float*)d_in[0];
    const float* context_feats = (const float*)d_in[1];
    const float* target_pos    = (const float*)d_in[2];
    const float* context_pos   = (const float*)d_in[3];
    const float* W_proj        = (const float*)d_in[4];
    const float* b_proj        = (const float*)d_in[5];
    const float* Wq            = (const float*)d_in[6];
    const float* Wk            = (const float*)d_in[7];
    const float* Wv            = (const float*)d_in[8];
    const float* Wo            = (const float*)d_in[9];
    const float* ln1_s         = (const float*)d_in[10];
    const float* ln1_b         = (const float*)d_in[11];
    const float* ln2_s         = (const float*)d_in[12];
    const float* ln2_b         = (const float*)d_in[13];
    const float* W1            = (const float*)d_in[14];
    const float* b1            = (const float*)d_in[15];
    const float* W2            = (const float*)d_in[16];
    const float* b2            = (const float*)d_in[17];
    const float* lnf_s         = (const float*)d_in[18];
    const float* lnf_b         = (const float*)d_in[19];
    float* out = (float*)d_out;

    float *x, *h, *q, *k, *v, *accb, *ffn;
    cudaGetSymbolAddress((void**)&x,    g_x);
    cudaGetSymbolAddress((void**)&h,    g_h);
    cudaGetSymbolAddress((void**)&q,    g_q);
    cudaGetSymbolAddress((void**)&k,    g_k);
    cudaGetSymbolAddress((void**)&v,    g_v);
    cudaGetSymbolAddress((void**)&accb, g_acc);
    cudaGetSymbolAddress((void**)&ffn,  g_ffn);

    const dim3 blk(256);
    const dim3 gN128 (DIM / 128, TOK / 64, 1);       // (2, 64)
    const dim3 gQKV  (DIM / 128, TOK / 64, 3);       // (2, 64, 3)
    const dim3 gKV   (DIM / 128, TOK / 64, 2);       // (2, 64, 2)
    const dim3 gFFN1 (FFN_DIM / 128, TOK / 64, 1);   // (8, 64)

    // 1. Projection (+bias +posenc fused), K=512 (register-prefetch GEMM)
    mma_gemm<5, true, false><<<gN128, blk>>>(
        nullptr, nullptr, nullptr, W_proj,
        b_proj, nullptr, x, DIM, INDIM,
        target_feat, context_feats, target_pos, context_pos);

    // ======================= Layer 1 (full) =======================
    ln_kernel<<<(TOK * 32) / 256, 256>>>(x, ln1_s, ln1_b, h, TOK, DIM);

    // QKV fused (pipelined)
    gemm_pipe<0><<<gQKV, blk>>>(h, Wq, Wk, Wv, nullptr, nullptr,
                                q, k, v, DIM, DIM);

    attn_all_kernel<<<896, 128>>>(q, k, v, accb, h, ffn);

    // Wo with masked 3-buffer A-sum + residual (register-prefetch GEMM)
    mma_gemm<3, false, true><<<gN128, blk>>>(
        accb, h, ffn, Wo,
        nullptr, x, x, DIM, DIM,
        nullptr, nullptr, nullptr, nullptr);

    ln_kernel<<<(TOK * 32) / 256, 256>>>(x, ln2_s, ln2_b, h, TOK, DIM);

    // FFN1: ffn = gelu(h @ W1 + b1) (pipelined)
    gemm_pipe<2><<<gFFN1, blk>>>(h, W1, nullptr, nullptr, b1, nullptr,
                                 ffn, nullptr, nullptr, FFN_DIM, DIM);

    // FFN2: x = ffn @ W2 + b2 + x (pipelined, K=1024)
    gemm_pipe<3><<<gN128, blk>>>(ffn, W2, nullptr, nullptr, b2, x,
                                 x, nullptr, nullptr, DIM, FFN_DIM);

    // ================== Layer 2 (token-0 truncated) ==================
    ln_kernel<<<(TOK * 32) / 256, 256>>>(x, ln1_s + DIM, ln1_b + DIM, h, TOK, DIM);

    // K,V full (pipelined, z=2)
    gemm_pipe<0><<<gKV, blk>>>(h, Wk + DIM * DIM, Wv + DIM * DIM, nullptr,
                               nullptr, nullptr, k, v, nullptr, DIM, DIM);

    tail_kernel<<<BATCH, blk>>>(
        x, h, k, v,
        Wq + DIM * DIM, Wo + DIM * DIM,
        W1 + DIM * FFN_DIM, W2 + FFN_DIM * DIM,
        b1 + FFN_DIM, b2 + DIM,
        ln2_s + DIM, ln2_b + DIM, lnf_s, lnf_b, out);
}

// round 12
// speedup vs baseline: 1.4151x; 1.0968x over previous
#include <cuda_runtime.h>
#include <math.h>

// ---------------------------------------------------------------------------
// GlobalLocalAwareEncoder — truncated-dependency implementation.
// T1: dilated segments never cross 256-token boundaries -> token 0 depends
//     only on tokens [0,256) per batch.
// T2: layer 2 is last -> only token 0 per batch feeds output (fused tail).
// All GEMMs: cp.async 3-stage pipelined tf32 MMA (raw-fp32 inputs, implicit
// RZ truncation). proj uses gathered A rows + posenc epilogue.
// Attention: tf32 m16n8k8, one launch; all 3 configs atomicAdd into one
// zeroed buffer -> Wo is a plain pipelined GEMM.
// ---------------------------------------------------------------------------

#define BATCH   16
#define SEQ     256
#define TOK     (BATCH * SEQ)   // 4096
#define DIM     256
#define HEADS   8
#define HDIM    32
#define FFN_DIM 1024
#define INDIM   512
#define NCTX    4095

__device__ float g_x  [TOK * DIM];
__device__ float g_h  [TOK * DIM];     // LN output
__device__ float g_q  [TOK * DIM];
__device__ float g_k  [TOK * DIM];
__device__ float g_v  [TOK * DIM];
__device__ float g_acc[TOK * DIM];     // attention output (atomic-accumulated)
__device__ float g_ffn[TOK * FFN_DIM]; // FFN hidden

__device__ __forceinline__ float gelu_tanh(float x) {
    float x3 = x * x * x;
    return 0.5f * x * (1.0f + tanhf(0.7978845608028654f * (x + 0.044715f * x3)));
}

__device__ __forceinline__ void mma_tf32(float* d, uint4 a, unsigned b0, unsigned b1) {
    asm volatile(
        "mma.sync.aligned.m16n8k8.row.col.f32.tf32.tf32.f32 "
        "{%0,%1,%2,%3}, {%4,%5,%6,%7}, {%8,%9}, {%0,%1,%2,%3};"
        : "+f"(d[0]), "+f"(d[1]), "+f"(d[2]), "+f"(d[3])
        : "r"(a.x), "r"(a.y), "r"(a.z), "r"(a.w), "r"(b0), "r"(b1));
}

__device__ __forceinline__ void cpa16(unsigned dst, const float* src) {
    asm volatile("cp.async.cg.shared.global [%0], [%1], 16;" :: "r"(dst), "l"(src));
}

__device__ __forceinline__ float wred_sum(float v) {
#pragma unroll
    for (int o = 16; o > 0; o >>= 1) v += __shfl_xor_sync(0xffffffffu, v, o);
    return v;
}

// positional encoding value for (token row, channel col), dim=256
__device__ __forceinline__ float pe_val(int row, int col,
                                        const float* __restrict__ tpos,
                                        const float* __restrict__ cpos) {
    int b = row >> 8, s = row & 255;
    const float* pp = (s == 0) ? (tpos + (size_t)b * 2)
                               : (cpos + ((size_t)b * NCTX + (s - 1)) * 2);
    float pos = (col < 128) ? pp[0] : pp[1];
    int dd = col & 127;
    int i  = dd & 63;
    float omega = expf(-(float)i * (9.210340371976184f / 64.0f));
    float ang = pos * omega;
    return (dd < 64) ? sinf(ang) : cosf(ang);
}

// ---------------------------------------------------------------------------
// Pipelined tf32 GEMM. C[4096,N] = A[4096,K] @ B[K,N].
// BM=64, BN=128, BK=16, 3-stage cp.async ring, 256 threads (8 warps, 32x32).
// GATHER: A rows come from target_feat / context_feats (K == INDIM).
// EPI: 0 store / 2 gelu(v+bias) / 3 v+res(+bias) / 5 v+bias+0.3*posenc
// blockIdx.z selects B/C.
// ---------------------------------------------------------------------------
#define PAS 1280   // 64 * 20 words per A stage
#define PBS 2176   // 16 * 136 words per B stage

template<int EPI, bool GATHER>
__global__ __launch_bounds__(256)
void gemm_pipe(const float* __restrict__ A,
               const float* __restrict__ B0, const float* __restrict__ B1,
               const float* __restrict__ B2,
               const float* __restrict__ bias, const float* __restrict__ res,
               float* __restrict__ C0, float* __restrict__ C1, float* __restrict__ C2,
               int N, int K,
               const float* __restrict__ tfeat, const float* __restrict__ cfeat,
               const float* __restrict__ tpos,  const float* __restrict__ cpos)
{
    __shared__ float sm[3 * (PAS + PBS)];   // 41472 B
    float* AsB = sm;
    float* BsB = sm + 3 * PAS;

    const int z = blockIdx.z;
    const float* B = (z == 0) ? B0 : (z == 1) ? B1 : B2;
    float*       C = (z == 0) ? C0 : (z == 1) ? C1 : C2;

    const int t    = threadIdx.x;
    const int lane = t & 31;
    const int warp = t >> 5;
    const int wm   = warp >> 2;
    const int wn   = warp & 3;
    const int gid  = lane >> 2;
    const int tig  = lane & 3;

    const int bm = blockIdx.y * 64;
    const int bn = blockIdx.x * 128;

    // ---- cp.async source/dest mapping ----
    const int arow = t >> 2;            // 0..63
    const int akq  = (t & 3) * 4;       // 0,4,8,12
    const float* aptr;
    if (GATHER) {
        int row = bm + arow;
        int bi = row >> 8, s = row & 255;
        const float* rp = (s == 0) ? (tfeat + (size_t)bi * INDIM)
                                   : (cfeat + ((size_t)bi * NCTX + (s - 1)) * INDIM);
        aptr = rp + akq;
    } else {
        aptr = A + (size_t)(bm + arow) * K + akq;
    }
    const unsigned a_dst = (unsigned)__cvta_generic_to_shared(AsB + arow * 20 + akq);

    const int kr0 = t >> 5;             // 0..7
    const int nq  = (t & 31) * 4;       // 0..124
    const float* bptr0 = B + (size_t)kr0 * N + bn + nq;
    const float* bptr1 = B + (size_t)(kr0 + 8) * N + bn + nq;
    const unsigned b_dst0 = (unsigned)__cvta_generic_to_shared(BsB + kr0 * 136 + nq);
    const unsigned b_dst1 = (unsigned)__cvta_generic_to_shared(BsB + (kr0 + 8) * 136 + nq);

    const int nchunks = K >> 4;

    auto issue = [&](int c) {
        if (c < nchunks) {
            int st = c % 3;
            cpa16(a_dst  + st * PAS * 4, aptr  + c * 16);
            cpa16(b_dst0 + st * PBS * 4, bptr0 + (size_t)c * 16 * N);
            cpa16(b_dst1 + st * PBS * 4, bptr1 + (size_t)c * 16 * N);
        }
        asm volatile("cp.async.commit_group;");
    };

    float accd[2][4][4];
#pragma unroll
    for (int mf = 0; mf < 2; mf++)
#pragma unroll
        for (int nf = 0; nf < 4; nf++)
#pragma unroll
            for (int r = 0; r < 4; r++) accd[mf][nf][r] = 0.f;

    issue(0);
    issue(1);

    for (int c = 0; c < nchunks; c++) {
        asm volatile("cp.async.wait_group 1;");
        __syncthreads();
        issue(c + 2);

        const int st = c % 3;
        const float* Asp = AsB + st * PAS;
        const float* Bsp = BsB + st * PBS;
#pragma unroll
        for (int kf = 0; kf < 2; kf++) {
            uint4 afr[2];
#pragma unroll
            for (int mf = 0; mf < 2; mf++) {
                int rb = wm * 32 + mf * 16;
                afr[mf].x = __float_as_uint(Asp[(rb + gid)     * 20 + kf * 8 + tig]);
                afr[mf].y = __float_as_uint(Asp[(rb + 8 + gid) * 20 + kf * 8 + tig]);
                afr[mf].z = __float_as_uint(Asp[(rb + gid)     * 20 + kf * 8 + tig + 4]);
                afr[mf].w = __float_as_uint(Asp[(rb + 8 + gid) * 20 + kf * 8 + tig + 4]);
            }
#pragma unroll
            for (int nf = 0; nf < 4; nf++) {
                int cb = wn * 32 + nf * 8 + gid;
                unsigned bb0 = __float_as_uint(Bsp[(kf * 8 + tig)     * 136 + cb]);
                unsigned bb1 = __float_as_uint(Bsp[(kf * 8 + tig + 4) * 136 + cb]);
                mma_tf32(accd[0][nf], afr[0], bb0, bb1);
                mma_tf32(accd[1][nf], afr[1], bb0, bb1);
            }
        }
    }

    // ---- epilogue ----
#pragma unroll
    for (int mf = 0; mf < 2; mf++) {
#pragma unroll
        for (int nf = 0; nf < 4; nf++) {
            int row = bm + wm * 32 + mf * 16 + gid;
            int col = bn + wn * 32 + nf * 8 + 2 * tig;
#pragma unroll
            for (int half = 0; half < 2; half++) {
                int r = row + half * 8;
                float v0 = accd[mf][nf][half * 2 + 0];
                float v1 = accd[mf][nf][half * 2 + 1];
                size_t idx = (size_t)r * N + col;
                if (EPI == 2) {
                    v0 = gelu_tanh(v0 + bias[col]);
                    v1 = gelu_tanh(v1 + bias[col + 1]);
                } else if (EPI == 3) {
                    if (bias) { v0 += bias[col]; v1 += bias[col + 1]; }
                    v0 += res[idx]; v1 += res[idx + 1];
                } else if (EPI == 5) {
                    v0 += bias[col]     + 0.3f * pe_val(r, col,     tpos, cpos);
                    v1 += bias[col + 1] + 0.3f * pe_val(r, col + 1, tpos, cpos);
                }
                *(float2*)&C[idx] = make_float2(v0, v1);
            }
        }
    }
}

// ---------------------------------------------------------------------------
// LayerNorm: one warp per token, D=256.
// ---------------------------------------------------------------------------
__global__ void ln_kernel(const float* __restrict__ x, const float* __restrict__ sc,
                          const float* __restrict__ bi, float* __restrict__ out,
                          int ntok, int in_stride)
{
    int gw   = (blockIdx.x * blockDim.x + threadIdx.x) >> 5;
    int lane = threadIdx.x & 31;
    if (gw >= ntok) return;
    const float* xp = x + (size_t)gw * in_stride;
    float4 v0 = *(const float4*)&xp[lane * 4];
    float4 v1 = *(const float4*)&xp[128 + lane * 4];
    float va[8] = {v0.x, v0.y, v0.z, v0.w, v1.x, v1.y, v1.z, v1.w};

    float s = 0.f;
#pragma unroll
    for (int c = 0; c < 8; c++) s += va[c];
    s = wred_sum(s);
    float mu = s * (1.0f / 256.0f);

    float ss = 0.f;
#pragma unroll
    for (int c = 0; c < 8; c++) { float d = va[c] - mu; ss += d * d; }
    ss = wred_sum(ss);
    float inv = rsqrtf(ss * (1.0f / 256.0f) + 1e-5f);

    float ovals[8];
#pragma unroll
    for (int c = 0; c < 8; c++) {
        int d = (c < 4) ? (lane * 4 + c) : (128 + lane * 4 + (c - 4));
        ovals[c] = (va[c] - mu) * inv * sc[d] + bi[d];
    }
    float* op = out + (size_t)gw * 256;
    *(float4*)&op[lane * 4]       = make_float4(ovals[0], ovals[1], ovals[2], ovals[3]);
    *(float4*)&op[128 + lane * 4] = make_float4(ovals[4], ovals[5], ovals[6], ovals[7]);
}

// ---------------------------------------------------------------------------
// Layer-1 dilated attention on tf32 tensor cores (grid 896, 128 threads).
// Q/K/V filled via cp.async as RAW fp32 (mma truncates); P stored raw fp32.
// All configs atomicAdd o/3 into acc (zeroed before launch).
// ---------------------------------------------------------------------------
__global__ __launch_bounds__(128)
void attn_all_kernel(const float* __restrict__ q, const float* __restrict__ k,
                     const float* __restrict__ v, float* __restrict__ acc)
{
    __shared__ unsigned sh[64 * 36 * 2 + 64 * 40];   // 28KB
    unsigned* qs  = sh;                 // [64][36]
    unsigned* ks  = sh + 64 * 36;       // [64][36]
    unsigned* vs  = sh + 64 * 72;       // [64][40]
    unsigned* smP = sh;                 // [64][68] overlays qs+ks

    int bid = blockIdx.x;
    int r, w;
    if (bid < 512)      { w = 64;  r = 1; }
    else if (bid < 768) { bid -= 512; w = 128; r = 2; }
    else                { bid -= 768; w = 256; r = 4; }

    const int nseg = SEQ / w;
    const int h   = bid & 7;
    const int seg = (bid >> 3) % nseg;
    const int b   = bid / (8 * nseg);
    const int base = b * SEQ + seg * w;
    const int off  = h % r;
    const int t    = threadIdx.x;
    const int lane = t & 31;
    const int wrp  = t >> 5;
    const int gid  = lane >> 2;
    const int tig  = lane & 3;

    // ---- fill Q,K,V via cp.async (raw fp32) ----
#pragma unroll
    for (int i = 0; i < 4; i++) {
        int idx = t + 128 * i;          // 0..511
        int j  = idx >> 3;
        int dq = (idx & 7) * 4;
        int tok = base + off + r * j;
        size_t gi = (size_t)tok * DIM + h * HDIM + dq;
        cpa16((unsigned)__cvta_generic_to_shared(&qs[j * 36 + dq]), &q[gi]);
        cpa16((unsigned)__cvta_generic_to_shared(&ks[j * 36 + dq]), &k[gi]);
        cpa16((unsigned)__cvta_generic_to_shared(&vs[j * 40 + dq]), &v[gi]);
    }
    asm volatile("cp.async.commit_group;");
    asm volatile("cp.async.wait_group 0;");
    __syncthreads();

    // ---- QK: S[16 rows x 64 cols] per warp, k=32 (4 steps) ----
    const int rA = wrp * 16 + gid;
    const int rB = rA + 8;
    float sacc[8][4];
#pragma unroll
    for (int nf = 0; nf < 8; nf++)
#pragma unroll
        for (int c = 0; c < 4; c++) sacc[nf][c] = 0.f;

#pragma unroll
    for (int kc = 0; kc < 4; kc++) {
        uint4 afr;
        afr.x = qs[rA * 36 + kc * 8 + tig];
        afr.y = qs[rB * 36 + kc * 8 + tig];
        afr.z = qs[rA * 36 + kc * 8 + tig + 4];
        afr.w = qs[rB * 36 + kc * 8 + tig + 4];
#pragma unroll
        for (int nf = 0; nf < 8; nf++) {
            unsigned bb0 = ks[(nf * 8 + gid) * 36 + kc * 8 + tig];
            unsigned bb1 = ks[(nf * 8 + gid) * 36 + kc * 8 + tig + 4];
            mma_tf32(sacc[nf], afr, bb0, bb1);
        }
    }

    // ---- softmax rows rA (c0,c1) / rB (c2,c3) ----
    const float scl = 0.17677669529663687f;
    float mA = -1e30f, mB = -1e30f;
#pragma unroll
    for (int nf = 0; nf < 8; nf++) {
        sacc[nf][0] *= scl; sacc[nf][1] *= scl;
        sacc[nf][2] *= scl; sacc[nf][3] *= scl;
        mA = fmaxf(mA, fmaxf(sacc[nf][0], sacc[nf][1]));
        mB = fmaxf(mB, fmaxf(sacc[nf][2], sacc[nf][3]));
    }
#pragma unroll
    for (int o = 2; o > 0; o >>= 1) {
        mA = fmaxf(mA, __shfl_xor_sync(0xffffffffu, mA, o));
        mB = fmaxf(mB, __shfl_xor_sync(0xffffffffu, mB, o));
    }
    float sA = 0.f, sB = 0.f;
#pragma unroll
    for (int nf = 0; nf < 8; nf++) {
        sacc[nf][0] = __expf(sacc[nf][0] - mA); sA += sacc[nf][0];
        sacc[nf][1] = __expf(sacc[nf][1] - mA); sA += sacc[nf][1];
        sacc[nf][2] = __expf(sacc[nf][2] - mB); sB += sacc[nf][2];
        sacc[nf][3] = __expf(sacc[nf][3] - mB); sB += sacc[nf][3];
    }
#pragma unroll
    for (int o = 2; o > 0; o >>= 1) {
        sA += __shfl_xor_sync(0xffffffffu, sA, o);
        sB += __shfl_xor_sync(0xffffffffu, sB, o);
    }
    const float iA = 1.0f / sA, iB = 1.0f / sB;

    __syncthreads();   // all warps done reading qs/ks -> overlay smP

    // ---- write P (raw fp32) ----
#pragma unroll
    for (int nf = 0; nf < 8; nf++) {
        int col = nf * 8 + 2 * tig;
        uint2 pa = make_uint2(__float_as_uint(sacc[nf][0] * iA),
                              __float_as_uint(sacc[nf][1] * iA));
        uint2 pb = make_uint2(__float_as_uint(sacc[nf][2] * iB),
                              __float_as_uint(sacc[nf][3] * iB));
        *(uint2*)&smP[rA * 68 + col] = pa;
        *(uint2*)&smP[rB * 68 + col] = pb;
    }
    __syncthreads();

    // ---- PV: O[16 x 32] per warp ----
    float oacc[4][4];
#pragma unroll
    for (int nf = 0; nf < 4; nf++)
#pragma unroll
        for (int c = 0; c < 4; c++) oacc[nf][c] = 0.f;

#pragma unroll
    for (int kc = 0; kc < 8; kc++) {
        uint4 afr;
        afr.x = smP[rA * 68 + kc * 8 + tig];
        afr.y = smP[rB * 68 + kc * 8 + tig];
        afr.z = smP[rA * 68 + kc * 8 + tig + 4];
        afr.w = smP[rB * 68 + kc * 8 + tig + 4];
#pragma unroll
        for (int nf = 0; nf < 4; nf++) {
            unsigned bb0 = vs[(kc * 8 + tig) * 40 + nf * 8 + gid];
            unsigned bb1 = vs[(kc * 8 + tig + 4) * 40 + nf * 8 + gid];
            mma_tf32(oacc[nf], afr, bb0, bb1);
        }
    }

    // ---- atomicAdd O/3 into acc ----
    const float third = 1.0f / 3.0f;
    const int tokA = base + off + r * rA;
    const int tokB = base + off + r * rB;
#pragma unroll
    for (int nf = 0; nf < 4; nf++) {
        int col = h * HDIM + nf * 8 + 2 * tig;
        float* pA = &acc[(size_t)tokA * DIM + col];
        float* pB = &acc[(size_t)tokB * DIM + col];
        atomicAdd(pA,     oacc[nf][0] * third);
        atomicAdd(pA + 1, oacc[nf][1] * third);
        atomicAdd(pB,     oacc[nf][2] * third);
        atomicAdd(pB + 1, oacc[nf][3] * third);
    }
}

// ---------------------------------------------------------------------------
// Layer-2 fused tail (per batch): q gemv, token-0 attn, Wo+res, LN2, FFN, LNf.
// ---------------------------------------------------------------------------
__global__ __launch_bounds__(256)
void tail_kernel(const float* __restrict__ x,  const float* __restrict__ hh,
                 const float* __restrict__ k,  const float* __restrict__ v,
                 const float* __restrict__ Wq, const float* __restrict__ Wo,
                 const float* __restrict__ W1, const float* __restrict__ W2,
                 const float* __restrict__ b1v, const float* __restrict__ b2v,
                 const float* __restrict__ ln2s, const float* __restrict__ ln2b,
                 const float* __restrict__ lnfs, const float* __restrict__ lnfb,
                 float* __restrict__ out)
{
    __shared__ float xs[256], hq[256], qsh[256], att[256], x1[256], h2[256];
    __shared__ float f[1024];
    __shared__ float red[4 * 256];
    __shared__ float psh[8][64];
    __shared__ float rsum[8];

    const int b    = blockIdx.x;
    const int t    = threadIdx.x;
    const int lane = t & 31;
    const int wrp  = t >> 5;
    const size_t row0 = (size_t)b * SEQ * DIM;

    xs[t] = x[row0 + t];
    hq[t] = hh[row0 + t];
    __syncthreads();

    {
        const int c4 = (t & 63) * 4;
        const int ks = t >> 6;
        float4 a = make_float4(0.f, 0.f, 0.f, 0.f);
        for (int kk = 0; kk < 64; kk++) {
            int ki = ks * 64 + kk;
            float s = hq[ki];
            float4 w = *(const float4*)&Wq[(size_t)ki * 256 + c4];
            a.x += s * w.x; a.y += s * w.y; a.z += s * w.z; a.w += s * w.w;
        }
        *(float4*)&red[ks * 256 + c4] = a;
        __syncthreads();
        qsh[t] = red[t] + red[256 + t] + red[512 + t] + red[768 + t];
        __syncthreads();
    }

    {
        const int h = wrp;
        float o = 0.f;
        const float4* qv = (const float4*)&qsh[h * 32];
#pragma unroll
        for (int c = 0; c < 3; c++) {
            const int r = 1 << c;
            if (h % r == 0) {
                const float4* k0p = (const float4*)(k + ((size_t)(b * 256 + r * lane) * DIM) + h * 32);
                const float4* k1p = (const float4*)(k + ((size_t)(b * 256 + r * (lane + 32)) * DIM) + h * 32);
                float s0 = 0.f, s1 = 0.f;
#pragma unroll
                for (int u = 0; u < 8; u++) {
                    float4 qd = qv[u];
                    float4 ka = k0p[u];
                    float4 kb = k1p[u];
                    s0 += qd.x * ka.x + qd.y * ka.y + qd.z * ka.z + qd.w * ka.w;
                    s1 += qd.x * kb.x + qd.y * kb.y + qd.z * kb.z + qd.w * kb.w;
                }
                s0 *= 0.17677669529663687f;
                s1 *= 0.17677669529663687f;
                float mx = fmaxf(s0, s1);
#pragma unroll
                for (int ofs = 16; ofs > 0; ofs >>= 1)
                    mx = fmaxf(mx, __shfl_xor_sync(0xffffffffu, mx, ofs));
                float e0 = __expf(s0 - mx), e1 = __expf(s1 - mx);
                float sm = wred_sum(e0 + e1);
                float inv = 1.0f / sm;
                psh[h][lane]      = e0 * inv;
                psh[h][lane + 32] = e1 * inv;
                __syncwarp();
                float oc = 0.f;
#pragma unroll 8
                for (int j = 0; j < 64; j++)
                    oc += psh[h][j] * v[((size_t)(b * 256 + r * j) * DIM) + h * 32 + lane];
                o += oc;
                __syncwarp();
            }
        }
        att[h * 32 + lane] = o * (1.0f / 3.0f);
    }
    __syncthreads();

    {
        const int c4 = (t & 63) * 4;
        const int ks = t >> 6;
        float4 a = make_float4(0.f, 0.f, 0.f, 0.f);
        for (int kk = 0; kk < 64; kk++) {
            int ki = ks * 64 + kk;
            float s = att[ki];
            float4 w = *(const float4*)&Wo[(size_t)ki * 256 + c4];
            a.x += s * w.x; a.y += s * w.y; a.z += s * w.z; a.w += s * w.w;
        }
        __syncthreads();
        *(float4*)&red[ks * 256 + c4] = a;
        __syncthreads();
        x1[t] = red[t] + red[256 + t] + red[512 + t] + red[768 + t] + xs[t];
        __syncthreads();
    }

    {
        float val = x1[t];
        float s = wred_sum(val);
        if (lane == 0) rsum[wrp] = s;
        __syncthreads();
        float tot = 0.f;
#pragma unroll
        for (int i = 0; i < 8; i++) tot += rsum[i];
        float mu = tot * (1.0f / 256.0f);
        __syncthreads();
        float dv = val - mu;
        float s2 = wred_sum(dv * dv);
        if (lane == 0) rsum[wrp] = s2;
        __syncthreads();
        float tv = 0.f;
#pragma unroll
        for (int i = 0; i < 8; i++) tv += rsum[i];
        float inv = rsqrtf(tv * (1.0f / 256.0f) + 1e-5f);
        h2[t] = dv * inv * ln2s[t] + ln2b[t];
        __syncthreads();
    }

    {
        const int c4 = t * 4;
        float4 a = make_float4(0.f, 0.f, 0.f, 0.f);
        for (int ki = 0; ki < 256; ki++) {
            float s = h2[ki];
            float4 w = *(const float4*)&W1[(size_t)ki * 1024 + c4];
            a.x += s * w.x; a.y += s * w.y; a.z += s * w.z; a.w += s * w.w;
        }
        float4 bb = *(const float4*)&b1v[c4];
        f[c4 + 0] = gelu_tanh(a.x + bb.x);
        f[c4 + 1] = gelu_tanh(a.y + bb.y);
        f[c4 + 2] = gelu_tanh(a.z + bb.z);
        f[c4 + 3] = gelu_tanh(a.w + bb.w);
        __syncthreads();
    }

    {
        const int c4 = (t & 63) * 4;
        const int ks = t >> 6;
        float4 a = make_float4(0.f, 0.f, 0.f, 0.f);
        for (int kk = 0; kk < 256; kk++) {
            int ki = ks * 256 + kk;
            float s = f[ki];
            float4 w = *(const float4*)&W2[(size_t)ki * 256 + c4];
            a.x += s * w.x; a.y += s * w.y; a.z += s * w.z; a.w += s * w.w;
        }
        *(float4*)&red[ks * 256 + c4] = a;
        __syncthreads();
        float y = red[t] + red[256 + t] + red[512 + t] + red[768 + t] + b2v[t] + x1[t];

        float s = wred_sum(y);
        if (lane == 0) rsum[wrp] = s;
        __syncthreads();
        float tot = 0.f;
#pragma unroll
        for (int i = 0; i < 8; i++) tot += rsum[i];
        float mu = tot * (1.0f / 256.0f);
        __syncthreads();
        float dv = y - mu;
        float s2 = wred_sum(dv * dv);
        if (lane == 0) rsum[wrp] = s2;
        __syncthreads();
        float tv = 0.f;
#pragma unroll
        for (int i = 0; i < 8; i++) tv += rsum[i];
        float inv = rsqrtf(tv * (1.0f / 256.0f) + 1e-5f);
        out[(size_t)b * 256 + t] = dv * inv * lnfs[t] + lnfb[t];
    }
}

// ---------------------------------------------------------------------------
// Orchestration
// ---------------------------------------------------------------------------
extern "C" void kernel_launch(void* const* d_in, const int* in_sizes, int n_in,
                              void* d_out, int out_size)
{
    const float* target_feat   = (const float*)d_in[0];
    const float* context_feats = (const float*)d_in[1];
    const float* target_pos    = (const float*)d_in[2];
    const float* context_pos   = (const float*)d_in[3];
    const float* W_proj        = (const float*)d_in[4];
    const float* b_proj        = (const float*)d_in[5];
    const float* Wq            = (const float*)d_in[6];
    const float* Wk            = (const float*)d_in[7];
    const float* Wv            = (const float*)d_in[8];
    const float* Wo            = (const float*)d_in[9];
    const float* ln1_s         = (const float*)d_in[10];
    const float* ln1_b         = (const float*)d_in[11];
    const float* ln2_s         = (const float*)d_in[12];
    const float* ln2_b         = (const float*)d_in[13];
    const float* W1            = (const float*)d_in[14];
    const float* b1            = (const float*)d_in[15];
    const float* W2            = (const float*)d_in[16];
    const float* b2            = (const float*)d_in[17];
    const float* lnf_s         = (const float*)d_in[18];
    const float* lnf_b         = (const float*)d_in[19];
    float* out = (float*)d_out;

    float *x, *h, *q, *k, *v, *accb, *ffn;
    cudaGetSymbolAddress((void**)&x,    g_x);
    cudaGetSymbolAddress((void**)&h,    g_h);
    cudaGetSymbolAddress((void**)&q,    g_q);
    cudaGetSymbolAddress((void**)&k,    g_k);
    cudaGetSymbolAddress((void**)&v,    g_v);
    cudaGetSymbolAddress((void**)&accb, g_acc);
    cudaGetSymbolAddress((void**)&ffn,  g_ffn);

    const dim3 blk(256);
    const dim3 gN128 (DIM / 128, TOK / 64, 1);       // (2, 64)
    const dim3 gQKV  (DIM / 128, TOK / 64, 3);       // (2, 64, 3)
    const dim3 gKV   (DIM / 128, TOK / 64, 2);       // (2, 64, 2)
    const dim3 gFFN1 (FFN_DIM / 128, TOK / 64, 1);   // (8, 64)

    // 0. Zero attention accumulator (atomicAdd target)
    cudaMemsetAsync(accb, 0, (size_t)TOK * DIM * sizeof(float));

    // 1. Projection (+bias +posenc fused), K=512, gathered A (pipelined)
    gemm_pipe<5, true><<<gN128, blk>>>(
        nullptr, W_proj, nullptr, nullptr, b_proj, nullptr,
        x, nullptr, nullptr, DIM, INDIM,
        target_feat, context_feats, target_pos, context_pos);

    // ======================= Layer 1 (full) =======================
    ln_kernel<<<(TOK * 32) / 256, 256>>>(x, ln1_s, ln1_b, h, TOK, DIM);

    // QKV fused (pipelined)
    gemm_pipe<0, false><<<gQKV, blk>>>(h, Wq, Wk, Wv, nullptr, nullptr,
                                       q, k, v, DIM, DIM,
                                       nullptr, nullptr, nullptr, nullptr);

    // Attention (all configs atomic-add into accb)
    attn_all_kernel<<<896, 128>>>(q, k, v, accb);

    // Wo + residual (plain pipelined GEMM)
    gemm_pipe<3, false><<<gN128, blk>>>(accb, Wo, nullptr, nullptr, nullptr, x,
                                        x, nullptr, nullptr, DIM, DIM,
                                        nullptr, nullptr, nullptr, nullptr);

    ln_kernel<<<(TOK * 32) / 256, 256>>>(x, ln2_s, ln2_b, h, TOK, DIM);

    // FFN1: ffn = gelu(h @ W1 + b1)
    gemm_pipe<2, false><<<gFFN1, blk>>>(h, W1, nullptr, nullptr, b1, nullptr,
                                        ffn, nullptr, nullptr, FFN_DIM, DIM,
                                        nullptr, nullptr, nullptr, nullptr);

    // FFN2: x = ffn @ W2 + b2 + x (K=1024)
    gemm_pipe<3, false><<<gN128, blk>>>(ffn, W2, nullptr, nullptr, b2, x,
                                        x, nullptr, nullptr, DIM, FFN_DIM,
                                        nullptr, nullptr, nullptr, nullptr);

    // ================== Layer 2 (token-0 truncated) ==================
    ln_kernel<<<(TOK * 32) / 256, 256>>>(x, ln1_s + DIM, ln1_b + DIM, h, TOK, DIM);

    // K,V full (pipelined, z=2)
    gemm_pipe<0, false><<<gKV, blk>>>(h, Wk + DIM * DIM, Wv + DIM * DIM, nullptr,
                                      nullptr, nullptr, k, v, nullptr, DIM, DIM,
                                      nullptr, nullptr, nullptr, nullptr);

    tail_kernel<<<BATCH, blk>>>(
        x, h, k, v,
        Wq + DIM * DIM, Wo + DIM * DIM,
        W1 + DIM * FFN_DIM, W2 + FFN_DIM * DIM,
        b1 + FFN_DIM, b2 + DIM,
        ln2_s + DIM, ln2_b + DIM, lnf_s, lnf_b, out);
}

// round 13
// speedup vs baseline: 1.4333x; 1.0128x over previous
#include <cuda_runtime.h>
#include <math.h>

// ---------------------------------------------------------------------------
// GlobalLocalAwareEncoder — truncated-dependency implementation.
// T1: dilated segments never cross 256-token boundaries -> token 0 depends
//     only on tokens [0,256) per batch.
// T2: layer 2 is last -> only token 0 per batch feeds output (fused tail).
// T3: token-0's layer-2 attention reads keys only at a 128-token compact set
//     per batch -> the whole post-attention path (Wo/LN2/FFN/LN/KV) runs on
//     2048 compact rows instead of 4096.
// All GEMMs: cp.async 3-stage pipelined tf32 MMA (raw fp32, implicit RZ).
// Compact GEMMs use BM=32/128-thread tiles to keep one full wave of CTAs.
// ---------------------------------------------------------------------------

#define BATCH   16
#define SEQ     256
#define TOK     (BATCH * SEQ)   // 4096
#define CTOK    (BATCH * 128)   // 2048 compact rows
#define DIM     256
#define HEADS   8
#define HDIM    32
#define FFN_DIM 1024
#define INDIM   512
#define NCTX    4095

__device__ float g_x  [TOK * DIM];     // proj out (full) -> later x2 compact
__device__ float g_h  [TOK * DIM];     // LN outputs (full then compact)
__device__ float g_q  [TOK * DIM];     // layer1 Q (full) -> later x1 compact
__device__ float g_k  [TOK * DIM];     // layer1 K (full) -> layer2 K compact
__device__ float g_v  [TOK * DIM];     // layer1 V (full) -> layer2 V compact
__device__ float g_acc[TOK * DIM];     // attention out (atomic, full)
__device__ float g_ffn[TOK * FFN_DIM]; // FFN hidden (compact rows used)

// compact index <-> token maps (per batch)
__device__ __forceinline__ int cmap(int c) {           // compact -> token
    return c < 64 ? c : (c < 96 ? 64 + 2 * (c - 64) : 128 + 4 * (c - 96));
}
__device__ __forceinline__ int cinv(int tok) {         // token -> compact
    return tok < 64 ? tok : (tok < 128 ? 64 + ((tok - 64) >> 1)
                                       : 96 + ((tok - 128) >> 2));
}

__device__ __forceinline__ float gelu_tanh(float x) {
    float x3 = x * x * x;
    return 0.5f * x * (1.0f + tanhf(0.7978845608028654f * (x + 0.044715f * x3)));
}

__device__ __forceinline__ void mma_tf32(float* d, uint4 a, unsigned b0, unsigned b1) {
    asm volatile(
        "mma.sync.aligned.m16n8k8.row.col.f32.tf32.tf32.f32 "
        "{%0,%1,%2,%3}, {%4,%5,%6,%7}, {%8,%9}, {%0,%1,%2,%3};"
        : "+f"(d[0]), "+f"(d[1]), "+f"(d[2]), "+f"(d[3])
        : "r"(a.x), "r"(a.y), "r"(a.z), "r"(a.w), "r"(b0), "r"(b1));
}

__device__ __forceinline__ void cpa16(unsigned dst, const float* src) {
    asm volatile("cp.async.cg.shared.global [%0], [%1], 16;" :: "r"(dst), "l"(src));
}

__device__ __forceinline__ float wred_sum(float v) {
#pragma unroll
    for (int o = 16; o > 0; o >>= 1) v += __shfl_xor_sync(0xffffffffu, v, o);
    return v;
}

__device__ __forceinline__ float pe_val(int row, int col,
                                        const float* __restrict__ tpos,
                                        const float* __restrict__ cpos) {
    int b = row >> 8, s = row & 255;
    const float* pp = (s == 0) ? (tpos + (size_t)b * 2)
                               : (cpos + ((size_t)b * NCTX + (s - 1)) * 2);
    float pos = (col < 128) ? pp[0] : pp[1];
    int dd = col & 127;
    int i  = dd & 63;
    float omega = expf(-(float)i * (9.210340371976184f / 64.0f));
    float ang = pos * omega;
    return (dd < 64) ? sinf(ang) : cosf(ang);
}

// ---------------------------------------------------------------------------
// Pipelined tf32 GEMM, BM=64, BN=128, BK=16, 3-stage, 256 threads.
// GATHER: A rows from target_feat/context_feats. blockIdx.z selects B/C.
// EPI: 0 store / 2 gelu(v+bias) / 5 v+bias+0.3*posenc
// ---------------------------------------------------------------------------
#define PAS 1280   // 64*20
#define PBS 2176   // 16*136

template<int EPI, bool GATHER>
__global__ __launch_bounds__(256)
void gemm_pipe(const float* __restrict__ A,
               const float* __restrict__ B0, const float* __restrict__ B1,
               const float* __restrict__ B2,
               const float* __restrict__ bias,
               float* __restrict__ C0, float* __restrict__ C1, float* __restrict__ C2,
               int N, int K,
               const float* __restrict__ tfeat, const float* __restrict__ cfeat,
               const float* __restrict__ tpos,  const float* __restrict__ cpos)
{
    __shared__ float sm[3 * (PAS + PBS)];
    float* AsB = sm;
    float* BsB = sm + 3 * PAS;

    const int z = blockIdx.z;
    const float* B = (z == 0) ? B0 : (z == 1) ? B1 : B2;
    float*       C = (z == 0) ? C0 : (z == 1) ? C1 : C2;

    const int t    = threadIdx.x;
    const int lane = t & 31;
    const int warp = t >> 5;
    const int wm   = warp >> 2;
    const int wn   = warp & 3;
    const int gid  = lane >> 2;
    const int tig  = lane & 3;

    const int bm = blockIdx.y * 64;
    const int bn = blockIdx.x * 128;

    const int arow = t >> 2;
    const int akq  = (t & 3) * 4;
    const float* aptr;
    if (GATHER) {
        int row = bm + arow;
        int bi = row >> 8, s = row & 255;
        const float* rp = (s == 0) ? (tfeat + (size_t)bi * INDIM)
                                   : (cfeat + ((size_t)bi * NCTX + (s - 1)) * INDIM);
        aptr = rp + akq;
    } else {
        aptr = A + (size_t)(bm + arow) * K + akq;
    }
    const unsigned a_dst = (unsigned)__cvta_generic_to_shared(AsB + arow * 20 + akq);

    const int kr0 = t >> 5;
    const int nq  = (t & 31) * 4;
    const float* bptr0 = B + (size_t)kr0 * N + bn + nq;
    const float* bptr1 = B + (size_t)(kr0 + 8) * N + bn + nq;
    const unsigned b_dst0 = (unsigned)__cvta_generic_to_shared(BsB + kr0 * 136 + nq);
    const unsigned b_dst1 = (unsigned)__cvta_generic_to_shared(BsB + (kr0 + 8) * 136 + nq);

    const int nchunks = K >> 4;

    auto issue = [&](int c) {
        if (c < nchunks) {
            int st = c % 3;
            cpa16(a_dst  + st * PAS * 4, aptr  + c * 16);
            cpa16(b_dst0 + st * PBS * 4, bptr0 + (size_t)c * 16 * N);
            cpa16(b_dst1 + st * PBS * 4, bptr1 + (size_t)c * 16 * N);
        }
        asm volatile("cp.async.commit_group;");
    };

    float accd[2][4][4];
#pragma unroll
    for (int mf = 0; mf < 2; mf++)
#pragma unroll
        for (int nf = 0; nf < 4; nf++)
#pragma unroll
            for (int r = 0; r < 4; r++) accd[mf][nf][r] = 0.f;

    issue(0);
    issue(1);

    for (int c = 0; c < nchunks; c++) {
        asm volatile("cp.async.wait_group 1;");
        __syncthreads();
        issue(c + 2);

        const int st = c % 3;
        const float* Asp = AsB + st * PAS;
        const float* Bsp = BsB + st * PBS;
#pragma unroll
        for (int kf = 0; kf < 2; kf++) {
            uint4 afr[2];
#pragma unroll
            for (int mf = 0; mf < 2; mf++) {
                int rb = wm * 32 + mf * 16;
                afr[mf].x = __float_as_uint(Asp[(rb + gid)     * 20 + kf * 8 + tig]);
                afr[mf].y = __float_as_uint(Asp[(rb + 8 + gid) * 20 + kf * 8 + tig]);
                afr[mf].z = __float_as_uint(Asp[(rb + gid)     * 20 + kf * 8 + tig + 4]);
                afr[mf].w = __float_as_uint(Asp[(rb + 8 + gid) * 20 + kf * 8 + tig + 4]);
            }
#pragma unroll
            for (int nf = 0; nf < 4; nf++) {
                int cb = wn * 32 + nf * 8 + gid;
                unsigned bb0 = __float_as_uint(Bsp[(kf * 8 + tig)     * 136 + cb]);
                unsigned bb1 = __float_as_uint(Bsp[(kf * 8 + tig + 4) * 136 + cb]);
                mma_tf32(accd[0][nf], afr[0], bb0, bb1);
                mma_tf32(accd[1][nf], afr[1], bb0, bb1);
            }
        }
    }

#pragma unroll
    for (int mf = 0; mf < 2; mf++) {
#pragma unroll
        for (int nf = 0; nf < 4; nf++) {
            int row = bm + wm * 32 + mf * 16 + gid;
            int col = bn + wn * 32 + nf * 8 + 2 * tig;
#pragma unroll
            for (int half = 0; half < 2; half++) {
                int r = row + half * 8;
                float v0 = accd[mf][nf][half * 2 + 0];
                float v1 = accd[mf][nf][half * 2 + 1];
                size_t idx = (size_t)r * N + col;
                if (EPI == 2) {
                    v0 = gelu_tanh(v0 + bias[col]);
                    v1 = gelu_tanh(v1 + bias[col + 1]);
                } else if (EPI == 5) {
                    v0 += bias[col]     + 0.3f * pe_val(r, col,     tpos, cpos);
                    v1 += bias[col + 1] + 0.3f * pe_val(r, col + 1, tpos, cpos);
                }
                *(float2*)&C[idx] = make_float2(v0, v1);
            }
        }
    }
}

// ---------------------------------------------------------------------------
// Pipelined tf32 GEMM, BM=32, BN=128, BK=16, 3-stage, 128 threads (4 warps,
// warp tile 32x32). For compact-row GEMMs (Wo / FFN2 / KV).
// AGATHER: A row (compact) gathered from full-token buffer via cmap.
// EPI: 0 store / 3 v+res (res = plain compact) / 6 v+res (res = full, cmap'd)
// blockIdx.z selects B/C.
// ---------------------------------------------------------------------------
#define PAS32 640    // 32*20
#define PBS32 2176   // 16*136

template<int EPI, bool AGATHER>
__global__ __launch_bounds__(128)
void gemm_pipe32(const float* __restrict__ A,
                 const float* __restrict__ B0, const float* __restrict__ B1,
                 const float* __restrict__ bias, const float* __restrict__ res,
                 float* __restrict__ C0, float* __restrict__ C1,
                 int N, int K)
{
    __shared__ float sm[3 * (PAS32 + PBS32)];   // 33792 B
    float* AsB = sm;
    float* BsB = sm + 3 * PAS32;

    const int z = blockIdx.z;
    const float* B = (z == 0) ? B0 : B1;
    float*       C = (z == 0) ? C0 : C1;

    const int t    = threadIdx.x;
    const int lane = t & 31;
    const int wn   = t >> 5;            // 0..3 (warp = n-tile)
    const int gid  = lane >> 2;
    const int tig  = lane & 3;

    const int bm = blockIdx.y * 32;
    const int bn = blockIdx.x * 128;

    // A cp.async: 32 rows x 16 k = 128 cpa16, 1/thread
    const int arow = t >> 2;            // 0..31
    const int akq  = (t & 3) * 4;
    const float* aptr;
    if (AGATHER) {
        int row = bm + arow;            // compact row
        int bi = row >> 7;
        int tok = cmap(row & 127);
        aptr = A + (size_t)(bi * 256 + tok) * K + akq;
    } else {
        aptr = A + (size_t)(bm + arow) * K + akq;
    }
    const unsigned a_dst = (unsigned)__cvta_generic_to_shared(AsB + arow * 20 + akq);

    // B cp.async: 16 x 128 = 512 cpa16, 4/thread
    int b_kr[4], b_nq[4];
#pragma unroll
    for (int i = 0; i < 4; i++) {
        int idx = t + 128 * i;
        b_kr[i] = idx >> 5;             // 0..15
        b_nq[i] = (idx & 31) * 4;
    }

    const int nchunks = K >> 4;

    auto issue = [&](int c) {
        if (c < nchunks) {
            int st = c % 3;
            cpa16(a_dst + st * PAS32 * 4, aptr + c * 16);
#pragma unroll
            for (int i = 0; i < 4; i++) {
                const float* src = B + (size_t)(c * 16 + b_kr[i]) * N + bn + b_nq[i];
                unsigned dst = (unsigned)__cvta_generic_to_shared(
                    BsB + st * PBS32 + b_kr[i] * 136 + b_nq[i]);
                cpa16(dst, src);
            }
        }
        asm volatile("cp.async.commit_group;");
    };

    float accd[2][4][4];
#pragma unroll
    for (int mf = 0; mf < 2; mf++)
#pragma unroll
        for (int nf = 0; nf < 4; nf++)
#pragma unroll
            for (int r = 0; r < 4; r++) accd[mf][nf][r] = 0.f;

    issue(0);
    issue(1);

    for (int c = 0; c < nchunks; c++) {
        asm volatile("cp.async.wait_group 1;");
        __syncthreads();
        issue(c + 2);

        const int st = c % 3;
        const float* Asp = AsB + st * PAS32;
        const float* Bsp = BsB + st * PBS32;
#pragma unroll
        for (int kf = 0; kf < 2; kf++) {
            uint4 afr[2];
#pragma unroll
            for (int mf = 0; mf < 2; mf++) {
                int rb = mf * 16;
                afr[mf].x = __float_as_uint(Asp[(rb + gid)     * 20 + kf * 8 + tig]);
                afr[mf].y = __float_as_uint(Asp[(rb + 8 + gid) * 20 + kf * 8 + tig]);
                afr[mf].z = __float_as_uint(Asp[(rb + gid)     * 20 + kf * 8 + tig + 4]);
                afr[mf].w = __float_as_uint(Asp[(rb + 8 + gid) * 20 + kf * 8 + tig + 4]);
            }
#pragma unroll
            for (int nf = 0; nf < 4; nf++) {
                int cb = wn * 32 + nf * 8 + gid;
                unsigned bb0 = __float_as_uint(Bsp[(kf * 8 + tig)     * 136 + cb]);
                unsigned bb1 = __float_as_uint(Bsp[(kf * 8 + tig + 4) * 136 + cb]);
                mma_tf32(accd[0][nf], afr[0], bb0, bb1);
                mma_tf32(accd[1][nf], afr[1], bb0, bb1);
            }
        }
    }

#pragma unroll
    for (int mf = 0; mf < 2; mf++) {
#pragma unroll
        for (int nf = 0; nf < 4; nf++) {
            int row = bm + mf * 16 + gid;
            int col = bn + wn * 32 + nf * 8 + 2 * tig;
#pragma unroll
            for (int half = 0; half < 2; half++) {
                int r = row + half * 8;                 // compact row
                float v0 = accd[mf][nf][half * 2 + 0];
                float v1 = accd[mf][nf][half * 2 + 1];
                size_t idx = (size_t)r * N + col;
                if (EPI == 3) {
                    if (bias) { v0 += bias[col]; v1 += bias[col + 1]; }
                    v0 += res[idx]; v1 += res[idx + 1];
                } else if (EPI == 6) {
                    int bi = r >> 7;
                    int tok = cmap(r & 127);
                    size_t ridx = (size_t)(bi * 256 + tok) * N + col;
                    v0 += res[ridx]; v1 += res[ridx + 1];
                }
                *(float2*)&C[idx] = make_float2(v0, v1);
            }
        }
    }
}

// ---------------------------------------------------------------------------
// LayerNorm: one warp per token, D=256.
// ---------------------------------------------------------------------------
__global__ void ln_kernel(const float* __restrict__ x, const float* __restrict__ sc,
                          const float* __restrict__ bi, float* __restrict__ out,
                          int ntok, int in_stride)
{
    int gw   = (blockIdx.x * blockDim.x + threadIdx.x) >> 5;
    int lane = threadIdx.x & 31;
    if (gw >= ntok) return;
    const float* xp = x + (size_t)gw * in_stride;
    float4 v0 = *(const float4*)&xp[lane * 4];
    float4 v1 = *(const float4*)&xp[128 + lane * 4];
    float va[8] = {v0.x, v0.y, v0.z, v0.w, v1.x, v1.y, v1.z, v1.w};

    float s = 0.f;
#pragma unroll
    for (int c = 0; c < 8; c++) s += va[c];
    s = wred_sum(s);
    float mu = s * (1.0f / 256.0f);

    float ss = 0.f;
#pragma unroll
    for (int c = 0; c < 8; c++) { float d = va[c] - mu; ss += d * d; }
    ss = wred_sum(ss);
    float inv = rsqrtf(ss * (1.0f / 256.0f) + 1e-5f);

    float ovals[8];
#pragma unroll
    for (int c = 0; c < 8; c++) {
        int d = (c < 4) ? (lane * 4 + c) : (128 + lane * 4 + (c - 4));
        ovals[c] = (va[c] - mu) * inv * sc[d] + bi[d];
    }
    float* op = out + (size_t)gw * 256;
    *(float4*)&op[lane * 4]       = make_float4(ovals[0], ovals[1], ovals[2], ovals[3]);
    *(float4*)&op[128 + lane * 4] = make_float4(ovals[4], ovals[5], ovals[6], ovals[7]);
}

// ---------------------------------------------------------------------------
// Layer-1 dilated attention on tf32 tensor cores (grid 896, 128 threads).
// Raw-fp32 smem; all configs atomicAdd o/3 into acc (zeroed).
// ---------------------------------------------------------------------------
__global__ __launch_bounds__(128)
void attn_all_kernel(const float* __restrict__ q, const float* __restrict__ k,
                     const float* __restrict__ v, float* __restrict__ acc)
{
    __shared__ unsigned sh[64 * 36 * 2 + 64 * 40];
    unsigned* qs  = sh;
    unsigned* ks  = sh + 64 * 36;
    unsigned* vs  = sh + 64 * 72;
    unsigned* smP = sh;

    int bid = blockIdx.x;
    int r, w;
    if (bid < 512)      { w = 64;  r = 1; }
    else if (bid < 768) { bid -= 512; w = 128; r = 2; }
    else                { bid -= 768; w = 256; r = 4; }

    const int nseg = SEQ / w;
    const int h   = bid & 7;
    const int seg = (bid >> 3) % nseg;
    const int b   = bid / (8 * nseg);
    const int base = b * SEQ + seg * w;
    const int off  = h % r;
    const int t    = threadIdx.x;
    const int lane = t & 31;
    const int wrp  = t >> 5;
    const int gid  = lane >> 2;
    const int tig  = lane & 3;

#pragma unroll
    for (int i = 0; i < 4; i++) {
        int idx = t + 128 * i;
        int j  = idx >> 3;
        int dq = (idx & 7) * 4;
        int tok = base + off + r * j;
        size_t gi = (size_t)tok * DIM + h * HDIM + dq;
        cpa16((unsigned)__cvta_generic_to_shared(&qs[j * 36 + dq]), &q[gi]);
        cpa16((unsigned)__cvta_generic_to_shared(&ks[j * 36 + dq]), &k[gi]);
        cpa16((unsigned)__cvta_generic_to_shared(&vs[j * 40 + dq]), &v[gi]);
    }
    asm volatile("cp.async.commit_group;");
    asm volatile("cp.async.wait_group 0;");
    __syncthreads();

    const int rA = wrp * 16 + gid;
    const int rB = rA + 8;
    float sacc[8][4];
#pragma unroll
    for (int nf = 0; nf < 8; nf++)
#pragma unroll
        for (int c = 0; c < 4; c++) sacc[nf][c] = 0.f;

#pragma unroll
    for (int kc = 0; kc < 4; kc++) {
        uint4 afr;
        afr.x = qs[rA * 36 + kc * 8 + tig];
        afr.y = qs[rB * 36 + kc * 8 + tig];
        afr.z = qs[rA * 36 + kc * 8 + tig + 4];
        afr.w = qs[rB * 36 + kc * 8 + tig + 4];
#pragma unroll
        for (int nf = 0; nf < 8; nf++) {
            unsigned bb0 = ks[(nf * 8 + gid) * 36 + kc * 8 + tig];
            unsigned bb1 = ks[(nf * 8 + gid) * 36 + kc * 8 + tig + 4];
            mma_tf32(sacc[nf], afr, bb0, bb1);
        }
    }

    const float scl = 0.17677669529663687f;
    float mA = -1e30f, mB = -1e30f;
#pragma unroll
    for (int nf = 0; nf < 8; nf++) {
        sacc[nf][0] *= scl; sacc[nf][1] *= scl;
        sacc[nf][2] *= scl; sacc[nf][3] *= scl;
        mA = fmaxf(mA, fmaxf(sacc[nf][0], sacc[nf][1]));
        mB = fmaxf(mB, fmaxf(sacc[nf][2], sacc[nf][3]));
    }
#pragma unroll
    for (int o = 2; o > 0; o >>= 1) {
        mA = fmaxf(mA, __shfl_xor_sync(0xffffffffu, mA, o));
        mB = fmaxf(mB, __shfl_xor_sync(0xffffffffu, mB, o));
    }
    float sA = 0.f, sB = 0.f;
#pragma unroll
    for (int nf = 0; nf < 8; nf++) {
        sacc[nf][0] = __expf(sacc[nf][0] - mA); sA += sacc[nf][0];
        sacc[nf][1] = __expf(sacc[nf][1] - mA); sA += sacc[nf][1];
        sacc[nf][2] = __expf(sacc[nf][2] - mB); sB += sacc[nf][2];
        sacc[nf][3] = __expf(sacc[nf][3] - mB); sB += sacc[nf][3];
    }
#pragma unroll
    for (int o = 2; o > 0; o >>= 1) {
        sA += __shfl_xor_sync(0xffffffffu, sA, o);
        sB += __shfl_xor_sync(0xffffffffu, sB, o);
    }
    const float iA = 1.0f / sA, iB = 1.0f / sB;

    __syncthreads();

#pragma unroll
    for (int nf = 0; nf < 8; nf++) {
        int col = nf * 8 + 2 * tig;
        uint2 pa = make_uint2(__float_as_uint(sacc[nf][0] * iA),
                              __float_as_uint(sacc[nf][1] * iA));
        uint2 pb = make_uint2(__float_as_uint(sacc[nf][2] * iB),
                              __float_as_uint(sacc[nf][3] * iB));
        *(uint2*)&smP[rA * 68 + col] = pa;
        *(uint2*)&smP[rB * 68 + col] = pb;
    }
    __syncthreads();

    float oacc[4][4];
#pragma unroll
    for (int nf = 0; nf < 4; nf++)
#pragma unroll
        for (int c = 0; c < 4; c++) oacc[nf][c] = 0.f;

#pragma unroll
    for (int kc = 0; kc < 8; kc++) {
        uint4 afr;
        afr.x = smP[rA * 68 + kc * 8 + tig];
        afr.y = smP[rB * 68 + kc * 8 + tig];
        afr.z = smP[rA * 68 + kc * 8 + tig + 4];
        afr.w = smP[rB * 68 + kc * 8 + tig + 4];
#pragma unroll
        for (int nf = 0; nf < 4; nf++) {
            unsigned bb0 = vs[(kc * 8 + tig) * 40 + nf * 8 + gid];
            unsigned bb1 = vs[(kc * 8 + tig + 4) * 40 + nf * 8 + gid];
            mma_tf32(oacc[nf], afr, bb0, bb1);
        }
    }

    const float third = 1.0f / 3.0f;
    const int tokA = base + off + r * rA;
    const int tokB = base + off + r * rB;
#pragma unroll
    for (int nf = 0; nf < 4; nf++) {
        int col = h * HDIM + nf * 8 + 2 * tig;
        float* pA = &acc[(size_t)tokA * DIM + col];
        float* pB = &acc[(size_t)tokB * DIM + col];
        atomicAdd(pA,     oacc[nf][0] * third);
        atomicAdd(pA + 1, oacc[nf][1] * third);
        atomicAdd(pB,     oacc[nf][2] * third);
        atomicAdd(pB + 1, oacc[nf][3] * third);
    }
}

// ---------------------------------------------------------------------------
// Layer-2 fused tail (per batch). Inputs are COMPACT buffers (128 rows/batch):
// x (= x2), hh (= LN1(x2)), k, v. Token 0 = compact row b*128.
// ---------------------------------------------------------------------------
__global__ __launch_bounds__(256)
void tail_kernel(const float* __restrict__ x,  const float* __restrict__ hh,
                 const float* __restrict__ k,  const float* __restrict__ v,
                 const float* __restrict__ Wq, const float* __restrict__ Wo,
                 const float* __restrict__ W1, const float* __restrict__ W2,
                 const float* __restrict__ b1v, const float* __restrict__ b2v,
                 const float* __restrict__ ln2s, const float* __restrict__ ln2b,
                 const float* __restrict__ lnfs, const float* __restrict__ lnfb,
                 float* __restrict__ out)
{
    __shared__ float xs[256], hq[256], qsh[256], att[256], x1[256], h2[256];
    __shared__ float f[1024];
    __shared__ float red[4 * 256];
    __shared__ float psh[8][64];
    __shared__ float rsum[8];

    const int b    = blockIdx.x;
    const int t    = threadIdx.x;
    const int lane = t & 31;
    const int wrp  = t >> 5;
    const size_t row0 = (size_t)b * 128 * DIM;   // compact token-0 row

    xs[t] = x[row0 + t];
    hq[t] = hh[row0 + t];
    __syncthreads();

    {
        const int c4 = (t & 63) * 4;
        const int ks = t >> 6;
        float4 a = make_float4(0.f, 0.f, 0.f, 0.f);
        for (int kk = 0; kk < 64; kk++) {
            int ki = ks * 64 + kk;
            float s = hq[ki];
            float4 w = *(const float4*)&Wq[(size_t)ki * 256 + c4];
            a.x += s * w.x; a.y += s * w.y; a.z += s * w.z; a.w += s * w.w;
        }
        *(float4*)&red[ks * 256 + c4] = a;
        __syncthreads();
        qsh[t] = red[t] + red[256 + t] + red[512 + t] + red[768 + t];
        __syncthreads();
    }

    {
        const int h = wrp;
        float o = 0.f;
        const float4* qv = (const float4*)&qsh[h * 32];
#pragma unroll
        for (int c = 0; c < 3; c++) {
            const int r = 1 << c;
            if (h % r == 0) {
                int c0 = cinv(r * lane);
                int c1 = cinv(r * (lane + 32));
                const float4* k0p = (const float4*)(k + ((size_t)(b * 128 + c0) * DIM) + h * 32);
                const float4* k1p = (const float4*)(k + ((size_t)(b * 128 + c1) * DIM) + h * 32);
                float s0 = 0.f, s1 = 0.f;
#pragma unroll
                for (int u = 0; u < 8; u++) {
                    float4 qd = qv[u];
                    float4 ka = k0p[u];
                    float4 kb = k1p[u];
                    s0 += qd.x * ka.x + qd.y * ka.y + qd.z * ka.z + qd.w * ka.w;
                    s1 += qd.x * kb.x + qd.y * kb.y + qd.z * kb.z + qd.w * kb.w;
                }
                s0 *= 0.17677669529663687f;
                s1 *= 0.17677669529663687f;
                float mx = fmaxf(s0, s1);
#pragma unroll
                for (int ofs = 16; ofs > 0; ofs >>= 1)
                    mx = fmaxf(mx, __shfl_xor_sync(0xffffffffu, mx, ofs));
                float e0 = __expf(s0 - mx), e1 = __expf(s1 - mx);
                float sm = wred_sum(e0 + e1);
                float inv = 1.0f / sm;
                psh[h][lane]      = e0 * inv;
                psh[h][lane + 32] = e1 * inv;
                __syncwarp();
                float oc = 0.f;
#pragma unroll 8
                for (int j = 0; j < 64; j++) {
                    int cj = cinv(r * j);
                    oc += psh[h][j] * v[((size_t)(b * 128 + cj) * DIM) + h * 32 + lane];
                }
                o += oc;
                __syncwarp();
            }
        }
        att[h * 32 + lane] = o * (1.0f / 3.0f);
    }
    __syncthreads();

    {
        const int c4 = (t & 63) * 4;
        const int ks = t >> 6;
        float4 a = make_float4(0.f, 0.f, 0.f, 0.f);
        for (int kk = 0; kk < 64; kk++) {
            int ki = ks * 64 + kk;
            float s = att[ki];
            float4 w = *(const float4*)&Wo[(size_t)ki * 256 + c4];
            a.x += s * w.x; a.y += s * w.y; a.z += s * w.z; a.w += s * w.w;
        }
        __syncthreads();
        *(float4*)&red[ks * 256 + c4] = a;
        __syncthreads();
        x1[t] = red[t] + red[256 + t] + red[512 + t] + red[768 + t] + xs[t];
        __syncthreads();
    }

    {
        float val = x1[t];
        float s = wred_sum(val);
        if (lane == 0) rsum[wrp] = s;
        __syncthreads();
        float tot = 0.f;
#pragma unroll
        for (int i = 0; i < 8; i++) tot += rsum[i];
        float mu = tot * (1.0f / 256.0f);
        __syncthreads();
        float dv = val - mu;
        float s2 = wred_sum(dv * dv);
        if (lane == 0) rsum[wrp] = s2;
        __syncthreads();
        float tv = 0.f;
#pragma unroll
        for (int i = 0; i < 8; i++) tv += rsum[i];
        float inv = rsqrtf(tv * (1.0f / 256.0f) + 1e-5f);
        h2[t] = dv * inv * ln2s[t] + ln2b[t];
        __syncthreads();
    }

    {
        const int c4 = t * 4;
        float4 a = make_float4(0.f, 0.f, 0.f, 0.f);
        for (int ki = 0; ki < 256; ki++) {
            float s = h2[ki];
            float4 w = *(const float4*)&W1[(size_t)ki * 1024 + c4];
            a.x += s * w.x; a.y += s * w.y; a.z += s * w.z; a.w += s * w.w;
        }
        float4 bb = *(const float4*)&b1v[c4];
        f[c4 + 0] = gelu_tanh(a.x + bb.x);
        f[c4 + 1] = gelu_tanh(a.y + bb.y);
        f[c4 + 2] = gelu_tanh(a.z + bb.z);
        f[c4 + 3] = gelu_tanh(a.w + bb.w);
        __syncthreads();
    }

    {
        const int c4 = (t & 63) * 4;
        const int ks = t >> 6;
        float4 a = make_float4(0.f, 0.f, 0.f, 0.f);
        for (int kk = 0; kk < 256; kk++) {
            int ki = ks * 256 + kk;
            float s = f[ki];
            float4 w = *(const float4*)&W2[(size_t)ki * 256 + c4];
            a.x += s * w.x; a.y += s * w.y; a.z += s * w.z; a.w += s * w.w;
        }
        *(float4*)&red[ks * 256 + c4] = a;
        __syncthreads();
        float y = red[t] + red[256 + t] + red[512 + t] + red[768 + t] + b2v[t] + x1[t];

        float s = wred_sum(y);
        if (lane == 0) rsum[wrp] = s;
        __syncthreads();
        float tot = 0.f;
#pragma unroll
        for (int i = 0; i < 8; i++) tot += rsum[i];
        float mu = tot * (1.0f / 256.0f);
        __syncthreads();
        float dv = y - mu;
        float s2 = wred_sum(dv * dv);
        if (lane == 0) rsum[wrp] = s2;
        __syncthreads();
        float tv = 0.f;
#pragma unroll
        for (int i = 0; i < 8; i++) tv += rsum[i];
        float inv = rsqrtf(tv * (1.0f / 256.0f) + 1e-5f);
        out[(size_t)b * 256 + t] = dv * inv * lnfs[t] + lnfb[t];
    }
}

// ---------------------------------------------------------------------------
// Orchestration
// ---------------------------------------------------------------------------
extern "C" void kernel_launch(void* const* d_in, const int* in_sizes, int n_in,
                              void* d_out, int out_size)
{
    const float* target_feat   = (const float*)d_in[0];
    const float* context_feats = (const float*)d_in[1];
    const float* target_pos    = (const float*)d_in[2];
    const float* context_pos   = (const float*)d_in[3];
    const float* W_proj        = (const float*)d_in[4];
    const float* b_proj        = (const float*)d_in[5];
    const float* Wq            = (const float*)d_in[6];
    const float* Wk            = (const float*)d_in[7];
    const float* Wv            = (const float*)d_in[8];
    const float* Wo            = (const float*)d_in[9];
    const float* ln1_s         = (const float*)d_in[10];
    const float* ln1_b         = (const float*)d_in[11];
    const float* ln2_s         = (const float*)d_in[12];
    const float* ln2_b         = (const float*)d_in[13];
    const float* W1            = (const float*)d_in[14];
    const float* b1            = (const float*)d_in[15];
    const float* W2            = (const float*)d_in[16];
    const float* b2            = (const float*)d_in[17];
    const float* lnf_s         = (const float*)d_in[18];
    const float* lnf_b         = (const float*)d_in[19];
    float* out = (float*)d_out;

    float *x, *h, *q, *k, *v, *accb, *ffn;
    cudaGetSymbolAddress((void**)&x,    g_x);
    cudaGetSymbolAddress((void**)&h,    g_h);
    cudaGetSymbolAddress((void**)&q,    g_q);
    cudaGetSymbolAddress((void**)&k,    g_k);
    cudaGetSymbolAddress((void**)&v,    g_v);
    cudaGetSymbolAddress((void**)&accb, g_acc);
    cudaGetSymbolAddress((void**)&ffn,  g_ffn);

    const dim3 gProj (DIM / 128, TOK / 64, 1);        // (2, 64)
    const dim3 gQKV  (DIM / 128, TOK / 64, 3);        // (2, 64, 3)
    const dim3 gWo   (DIM / 128, CTOK / 32, 1);       // (2, 64)
    const dim3 gFFN1 (FFN_DIM / 128, CTOK / 64, 1);   // (8, 32)
    const dim3 gFFN2 (DIM / 128, CTOK / 32, 1);       // (2, 64)
    const dim3 gKV   (DIM / 128, CTOK / 32, 2);       // (2, 64, 2)

    // 0. Zero attention accumulator
    cudaMemsetAsync(accb, 0, (size_t)TOK * DIM * sizeof(float));

    // 1. Projection (+bias +posenc), gathered A (full 4096 rows)
    gemm_pipe<5, true><<<gProj, 256>>>(
        nullptr, W_proj, nullptr, nullptr, b_proj,
        x, nullptr, nullptr, DIM, INDIM,
        target_feat, context_feats, target_pos, context_pos);

    // 2. LN1 (full)
    ln_kernel<<<(TOK * 32) / 256, 256>>>(x, ln1_s, ln1_b, h, TOK, DIM);

    // 3. QKV fused (full)
    gemm_pipe<0, false><<<gQKV, 256>>>(h, Wq, Wk, Wv, nullptr,
                                       q, k, v, DIM, DIM,
                                       nullptr, nullptr, nullptr, nullptr);

    // 4. Attention (atomic-add into accb, full)
    attn_all_kernel<<<896, 128>>>(q, k, v, accb);

    // 5. Wo + residual, COMPACT rows: A=acc (gathered), res=x (gathered) -> x1c (g_q)
    gemm_pipe32<6, true><<<gWo, 128>>>(accb, Wo, nullptr, nullptr, x,
                                       q, nullptr, DIM, DIM);

    // 6. LN2 compact: g_q -> g_h
    ln_kernel<<<(CTOK * 32) / 256, 256>>>(q, ln2_s, ln2_b, h, CTOK, DIM);

    // 7. FFN1 compact: ffn = gelu(h @ W1 + b1)
    gemm_pipe<2, false><<<gFFN1, 256>>>(h, W1, nullptr, nullptr, b1,
                                        ffn, nullptr, nullptr, FFN_DIM, DIM,
                                        nullptr, nullptr, nullptr, nullptr);

    // 8. FFN2 compact: x2c = ffn @ W2 + b2 + x1c -> g_x
    gemm_pipe32<3, false><<<gFFN2, 128>>>(ffn, W2, nullptr, b2, q,
                                          x, nullptr, DIM, FFN_DIM);

    // 9. LN1(l2) compact: g_x -> g_h
    ln_kernel<<<(CTOK * 32) / 256, 256>>>(x, ln1_s + DIM, ln1_b + DIM, h, CTOK, DIM);

    // 10. K,V compact (z=2)
    gemm_pipe32<0, false><<<gKV, 128>>>(h, Wk + DIM * DIM, Wv + DIM * DIM,
                                        nullptr, nullptr,
                                        k, v, DIM, DIM);

    // 11. Fused tail (compact inputs)
    tail_kernel<<<BATCH, 256>>>(
        x, h, k, v,
        Wq + DIM * DIM, Wo + DIM * DIM,
        W1 + DIM * FFN_DIM, W2 + FFN_DIM * DIM,
        b1 + FFN_DIM, b2 + DIM,
        ln2_s + DIM, ln2_b + DIM, lnf_s, lnf_b, out);
}

// round 14
// speedup vs baseline: 1.4630x; 1.0207x over previous
#include <cuda_runtime.h>
#include <math.h>

// ---------------------------------------------------------------------------
// GlobalLocalAwareEncoder — truncated-dependency implementation.
// T1: dilated segments never cross 256-token boundaries -> token 0 depends
//     only on tokens [0,256) per batch.
// T2: layer 2 is last -> only token 0 per batch feeds output (fused tail).
// T3: token-0's layer-2 attention reads a 128-token compact set per batch ->
//     post-attention path (Wo/LN2/FFN/LN/KV) runs on 2048 compact rows.
// All GEMMs: cp.async 3-stage pipelined tf32 MMA, BK=32 (dynamic smem),
// raw fp32 inputs (implicit RZ truncation).
// ---------------------------------------------------------------------------

#define BATCH   16
#define SEQ     256
#define TOK     (BATCH * SEQ)   // 4096
#define CTOK    (BATCH * 128)   // 2048 compact rows
#define DIM     256
#define HEADS   8
#define HDIM    32
#define FFN_DIM 1024
#define INDIM   512
#define NCTX    4095

__device__ float g_x  [TOK * DIM];
__device__ float g_h  [TOK * DIM];
__device__ float g_q  [TOK * DIM];
__device__ float g_k  [TOK * DIM];
__device__ float g_v  [TOK * DIM];
__device__ float g_acc[TOK * DIM];
__device__ float g_ffn[TOK * FFN_DIM];

// compact index <-> token maps (per batch)
__device__ __forceinline__ int cmap(int c) {
    return c < 64 ? c : (c < 96 ? 64 + 2 * (c - 64) : 128 + 4 * (c - 96));
}
__device__ __forceinline__ int cinv(int tok) {
    return tok < 64 ? tok : (tok < 128 ? 64 + ((tok - 64) >> 1)
                                       : 96 + ((tok - 128) >> 2));
}

__device__ __forceinline__ float gelu_tanh(float x) {
    float x3 = x * x * x;
    return 0.5f * x * (1.0f + tanhf(0.7978845608028654f * (x + 0.044715f * x3)));
}

__device__ __forceinline__ void mma_tf32(float* d, uint4 a, unsigned b0, unsigned b1) {
    asm volatile(
        "mma.sync.aligned.m16n8k8.row.col.f32.tf32.tf32.f32 "
        "{%0,%1,%2,%3}, {%4,%5,%6,%7}, {%8,%9}, {%0,%1,%2,%3};"
        : "+f"(d[0]), "+f"(d[1]), "+f"(d[2]), "+f"(d[3])
        : "r"(a.x), "r"(a.y), "r"(a.z), "r"(a.w), "r"(b0), "r"(b1));
}

__device__ __forceinline__ void cpa16(unsigned dst, const float* src) {
    asm volatile("cp.async.cg.shared.global [%0], [%1], 16;" :: "r"(dst), "l"(src));
}

__device__ __forceinline__ float wred_sum(float v) {
#pragma unroll
    for (int o = 16; o > 0; o >>= 1) v += __shfl_xor_sync(0xffffffffu, v, o);
    return v;
}

__device__ __forceinline__ float pe_val(int row, int col,
                                        const float* __restrict__ tpos,
                                        const float* __restrict__ cpos) {
    int b = row >> 8, s = row & 255;
    const float* pp = (s == 0) ? (tpos + (size_t)b * 2)
                               : (cpos + ((size_t)b * NCTX + (s - 1)) * 2);
    float pos = (col < 128) ? pp[0] : pp[1];
    int dd = col & 127;
    int i  = dd & 63;
    float omega = expf(-(float)i * (9.210340371976184f / 64.0f));
    float ang = pos * omega;
    return (dd < 64) ? sinf(ang) : cosf(ang);
}

// ---------------------------------------------------------------------------
// Pipelined tf32 GEMM, BM=64, BN=128, BK=32, 3-stage, 256 threads.
// Dynamic smem: 3*(64*36 + 32*136)*4 = 79872 B.
// GATHER: A rows from target_feat/context_feats. blockIdx.z selects B/C.
// EPI: 0 store / 2 gelu(v+bias) / 5 v+bias+0.3*posenc
// ---------------------------------------------------------------------------
#define PAS  2304   // 64*36 words per A stage
#define PBS  4352   // 32*136 words per B stage
#define GP_SMEM (3 * (PAS + PBS) * 4)

template<int EPI, bool GATHER>
__global__ __launch_bounds__(256)
void gemm_pipe(const float* __restrict__ A,
               const float* __restrict__ B0, const float* __restrict__ B1,
               const float* __restrict__ B2,
               const float* __restrict__ bias,
               float* __restrict__ C0, float* __restrict__ C1, float* __restrict__ C2,
               int N, int K,
               const float* __restrict__ tfeat, const float* __restrict__ cfeat,
               const float* __restrict__ tpos,  const float* __restrict__ cpos)
{
    extern __shared__ float sm[];
    float* AsB = sm;
    float* BsB = sm + 3 * PAS;

    const int z = blockIdx.z;
    const float* B = (z == 0) ? B0 : (z == 1) ? B1 : B2;
    float*       C = (z == 0) ? C0 : (z == 1) ? C1 : C2;

    const int t    = threadIdx.x;
    const int lane = t & 31;
    const int warp = t >> 5;
    const int wm   = warp >> 2;
    const int wn   = warp & 3;
    const int gid  = lane >> 2;
    const int tig  = lane & 3;

    const int bm = blockIdx.y * 64;
    const int bn = blockIdx.x * 128;

    // ---- A fill: 512 cpa16 per chunk, 2 per thread ----
    const float* aptr[2];
    unsigned a_dst[2];
#pragma unroll
    for (int i = 0; i < 2; i++) {
        int idx  = t + 256 * i;
        int arow = idx >> 3;            // 0..63
        int acq  = (idx & 7) * 4;       // 0..28
        if (GATHER) {
            int row = bm + arow;
            int bi = row >> 8, s = row & 255;
            const float* rp = (s == 0) ? (tfeat + (size_t)bi * INDIM)
                                       : (cfeat + ((size_t)bi * NCTX + (s - 1)) * INDIM);
            aptr[i] = rp + acq;
        } else {
            aptr[i] = A + (size_t)(bm + arow) * K + acq;
        }
        a_dst[i] = (unsigned)__cvta_generic_to_shared(AsB + arow * 36 + acq);
    }

    // ---- B fill: 1024 cpa16 per chunk, 4 per thread ----
    int b_kr[4], b_nq[4];
    unsigned b_dst[4];
#pragma unroll
    for (int i = 0; i < 4; i++) {
        int idx = t + 256 * i;
        b_kr[i] = idx >> 5;             // 0..31
        b_nq[i] = (idx & 31) * 4;
        b_dst[i] = (unsigned)__cvta_generic_to_shared(BsB + b_kr[i] * 136 + b_nq[i]);
    }

    const int nchunks = K >> 5;

    auto issue = [&](int c) {
        if (c < nchunks) {
            int st = c % 3;
            cpa16(a_dst[0] + st * PAS * 4, aptr[0] + c * 32);
            cpa16(a_dst[1] + st * PAS * 4, aptr[1] + c * 32);
#pragma unroll
            for (int i = 0; i < 4; i++) {
                const float* src = B + (size_t)(c * 32 + b_kr[i]) * N + bn + b_nq[i];
                cpa16(b_dst[i] + st * PBS * 4, src);
            }
        }
        asm volatile("cp.async.commit_group;");
    };

    float accd[2][4][4];
#pragma unroll
    for (int mf = 0; mf < 2; mf++)
#pragma unroll
        for (int nf = 0; nf < 4; nf++)
#pragma unroll
            for (int r = 0; r < 4; r++) accd[mf][nf][r] = 0.f;

    issue(0);
    issue(1);

    for (int c = 0; c < nchunks; c++) {
        asm volatile("cp.async.wait_group 1;");
        __syncthreads();
        issue(c + 2);

        const int st = c % 3;
        const float* Asp = AsB + st * PAS;
        const float* Bsp = BsB + st * PBS;
#pragma unroll
        for (int kf = 0; kf < 4; kf++) {
            uint4 afr[2];
#pragma unroll
            for (int mf = 0; mf < 2; mf++) {
                int rb = wm * 32 + mf * 16;
                afr[mf].x = __float_as_uint(Asp[(rb + gid)     * 36 + kf * 8 + tig]);
                afr[mf].y = __float_as_uint(Asp[(rb + 8 + gid) * 36 + kf * 8 + tig]);
                afr[mf].z = __float_as_uint(Asp[(rb + gid)     * 36 + kf * 8 + tig + 4]);
                afr[mf].w = __float_as_uint(Asp[(rb + 8 + gid) * 36 + kf * 8 + tig + 4]);
            }
#pragma unroll
            for (int nf = 0; nf < 4; nf++) {
                int cb = wn * 32 + nf * 8 + gid;
                unsigned bb0 = __float_as_uint(Bsp[(kf * 8 + tig)     * 136 + cb]);
                unsigned bb1 = __float_as_uint(Bsp[(kf * 8 + tig + 4) * 136 + cb]);
                mma_tf32(accd[0][nf], afr[0], bb0, bb1);
                mma_tf32(accd[1][nf], afr[1], bb0, bb1);
            }
        }
    }

#pragma unroll
    for (int mf = 0; mf < 2; mf++) {
#pragma unroll
        for (int nf = 0; nf < 4; nf++) {
            int row = bm + wm * 32 + mf * 16 + gid;
            int col = bn + wn * 32 + nf * 8 + 2 * tig;
#pragma unroll
            for (int half = 0; half < 2; half++) {
                int r = row + half * 8;
                float v0 = accd[mf][nf][half * 2 + 0];
                float v1 = accd[mf][nf][half * 2 + 1];
                size_t idx = (size_t)r * N + col;
                if (EPI == 2) {
                    v0 = gelu_tanh(v0 + bias[col]);
                    v1 = gelu_tanh(v1 + bias[col + 1]);
                } else if (EPI == 5) {
                    v0 += bias[col]     + 0.3f * pe_val(r, col,     tpos, cpos);
                    v1 += bias[col + 1] + 0.3f * pe_val(r, col + 1, tpos, cpos);
                }
                *(float2*)&C[idx] = make_float2(v0, v1);
            }
        }
    }
}

// ---------------------------------------------------------------------------
// Pipelined tf32 GEMM, BM=32, BN=128, BK=32, 3-stage, 128 threads (4 warps,
// warp tile 32x32). Dynamic smem: 3*(32*36 + 32*136)*4 = 66048 B.
// AGATHER: A row (compact) gathered from full-token buffer via cmap.
// EPI: 0 store / 3 v+res(+bias), compact res / 6 v+res, res full (cmap'd)
// blockIdx.z selects B/C.
// ---------------------------------------------------------------------------
#define PAS32 1152   // 32*36
#define PBS32 4352   // 32*136
#define GP32_SMEM (3 * (PAS32 + PBS32) * 4)

template<int EPI, bool AGATHER>
__global__ __launch_bounds__(128)
void gemm_pipe32(const float* __restrict__ A,
                 const float* __restrict__ B0, const float* __restrict__ B1,
                 const float* __restrict__ bias, const float* __restrict__ res,
                 float* __restrict__ C0, float* __restrict__ C1,
                 int N, int K)
{
    extern __shared__ float sm[];
    float* AsB = sm;
    float* BsB = sm + 3 * PAS32;

    const int z = blockIdx.z;
    const float* B = (z == 0) ? B0 : B1;
    float*       C = (z == 0) ? C0 : C1;

    const int t    = threadIdx.x;
    const int lane = t & 31;
    const int wn   = t >> 5;            // 0..3 (warp = n-tile)
    const int gid  = lane >> 2;
    const int tig  = lane & 3;

    const int bm = blockIdx.y * 32;
    const int bn = blockIdx.x * 128;

    // A fill: 256 cpa16/chunk, 2/thread
    const float* aptr[2];
    unsigned a_dst[2];
#pragma unroll
    for (int i = 0; i < 2; i++) {
        int idx  = t + 128 * i;
        int arow = idx >> 3;            // 0..31
        int acq  = (idx & 7) * 4;
        if (AGATHER) {
            int row = bm + arow;
            int bi = row >> 7;
            int tok = cmap(row & 127);
            aptr[i] = A + (size_t)(bi * 256 + tok) * K + acq;
        } else {
            aptr[i] = A + (size_t)(bm + arow) * K + acq;
        }
        a_dst[i] = (unsigned)__cvta_generic_to_shared(AsB + arow * 36 + acq);
    }

    // B fill: 1024 cpa16/chunk, 8/thread
    int b_kr[8], b_nq[8];
    unsigned b_dst[8];
#pragma unroll
    for (int i = 0; i < 8; i++) {
        int idx = t + 128 * i;
        b_kr[i] = idx >> 5;             // 0..31
        b_nq[i] = (idx & 31) * 4;
        b_dst[i] = (unsigned)__cvta_generic_to_shared(BsB + b_kr[i] * 136 + b_nq[i]);
    }

    const int nchunks = K >> 5;

    auto issue = [&](int c) {
        if (c < nchunks) {
            int st = c % 3;
            cpa16(a_dst[0] + st * PAS32 * 4, aptr[0] + c * 32);
            cpa16(a_dst[1] + st * PAS32 * 4, aptr[1] + c * 32);
#pragma unroll
            for (int i = 0; i < 8; i++) {
                const float* src = B + (size_t)(c * 32 + b_kr[i]) * N + bn + b_nq[i];
                cpa16(b_dst[i] + st * PBS32 * 4, src);
            }
        }
        asm volatile("cp.async.commit_group;");
    };

    float accd[2][4][4];
#pragma unroll
    for (int mf = 0; mf < 2; mf++)
#pragma unroll
        for (int nf = 0; nf < 4; nf++)
#pragma unroll
            for (int r = 0; r < 4; r++) accd[mf][nf][r] = 0.f;

    issue(0);
    issue(1);

    for (int c = 0; c < nchunks; c++) {
        asm volatile("cp.async.wait_group 1;");
        __syncthreads();
        issue(c + 2);

        const int st = c % 3;
        const float* Asp = AsB + st * PAS32;
        const float* Bsp = BsB + st * PBS32;
#pragma unroll
        for (int kf = 0; kf < 4; kf++) {
            uint4 afr[2];
#pragma unroll
            for (int mf = 0; mf < 2; mf++) {
                int rb = mf * 16;
                afr[mf].x = __float_as_uint(Asp[(rb + gid)     * 36 + kf * 8 + tig]);
                afr[mf].y = __float_as_uint(Asp[(rb + 8 + gid) * 36 + kf * 8 + tig]);
                afr[mf].z = __float_as_uint(Asp[(rb + gid)     * 36 + kf * 8 + tig + 4]);
                afr[mf].w = __float_as_uint(Asp[(rb + 8 + gid) * 36 + kf * 8 + tig + 4]);
            }
#pragma unroll
            for (int nf = 0; nf < 4; nf++) {
                int cb = wn * 32 + nf * 8 + gid;
                unsigned bb0 = __float_as_uint(Bsp[(kf * 8 + tig)     * 136 + cb]);
                unsigned bb1 = __float_as_uint(Bsp[(kf * 8 + tig + 4) * 136 + cb]);
                mma_tf32(accd[0][nf], afr[0], bb0, bb1);
                mma_tf32(accd[1][nf], afr[1], bb0, bb1);
            }
        }
    }

#pragma unroll
    for (int mf = 0; mf < 2; mf++) {
#pragma unroll
        for (int nf = 0; nf < 4; nf++) {
            int row = bm + mf * 16 + gid;
            int col = bn + wn * 32 + nf * 8 + 2 * tig;
#pragma unroll
            for (int half = 0; half < 2; half++) {
                int r = row + half * 8;                 // compact row
                float v0 = accd[mf][nf][half * 2 + 0];
                float v1 = accd[mf][nf][half * 2 + 1];
                size_t idx = (size_t)r * N + col;
                if (EPI == 3) {
                    if (bias) { v0 += bias[col]; v1 += bias[col + 1]; }
                    v0 += res[idx]; v1 += res[idx + 1];
                } else if (EPI == 6) {
                    int bi = r >> 7;
                    int tok = cmap(r & 127);
                    size_t ridx = (size_t)(bi * 256 + tok) * N + col;
                    v0 += res[ridx]; v1 += res[ridx + 1];
                }
                *(float2*)&C[idx] = make_float2(v0, v1);
            }
        }
    }
}

// ---------------------------------------------------------------------------
// LayerNorm: one warp per token, D=256.
// ---------------------------------------------------------------------------
__global__ void ln_kernel(const float* __restrict__ x, const float* __restrict__ sc,
                          const float* __restrict__ bi, float* __restrict__ out,
                          int ntok, int in_stride)
{
    int gw   = (blockIdx.x * blockDim.x + threadIdx.x) >> 5;
    int lane = threadIdx.x & 31;
    if (gw >= ntok) return;
    const float* xp = x + (size_t)gw * in_stride;
    float4 v0 = *(const float4*)&xp[lane * 4];
    float4 v1 = *(const float4*)&xp[128 + lane * 4];
    float va[8] = {v0.x, v0.y, v0.z, v0.w, v1.x, v1.y, v1.z, v1.w};

    float s = 0.f;
#pragma unroll
    for (int c = 0; c < 8; c++) s += va[c];
    s = wred_sum(s);
    float mu = s * (1.0f / 256.0f);

    float ss = 0.f;
#pragma unroll
    for (int c = 0; c < 8; c++) { float d = va[c] - mu; ss += d * d; }
    ss = wred_sum(ss);
    float inv = rsqrtf(ss * (1.0f / 256.0f) + 1e-5f);

    float ovals[8];
#pragma unroll
    for (int c = 0; c < 8; c++) {
        int d = (c < 4) ? (lane * 4 + c) : (128 + lane * 4 + (c - 4));
        ovals[c] = (va[c] - mu) * inv * sc[d] + bi[d];
    }
    float* op = out + (size_t)gw * 256;
    *(float4*)&op[lane * 4]       = make_float4(ovals[0], ovals[1], ovals[2], ovals[3]);
    *(float4*)&op[128 + lane * 4] = make_float4(ovals[4], ovals[5], ovals[6], ovals[7]);
}

// ---------------------------------------------------------------------------
// Layer-1 dilated attention on tf32 tensor cores (grid 896, 128 threads).
// Raw-fp32 smem; all configs atomicAdd o/3 into acc (zeroed).
// ---------------------------------------------------------------------------
__global__ __launch_bounds__(128)
void attn_all_kernel(const float* __restrict__ q, const float* __restrict__ k,
                     const float* __restrict__ v, float* __restrict__ acc)
{
    __shared__ unsigned sh[64 * 36 * 2 + 64 * 40];
    unsigned* qs  = sh;
    unsigned* ks  = sh + 64 * 36;
    unsigned* vs  = sh + 64 * 72;
    unsigned* smP = sh;

    int bid = blockIdx.x;
    int r, w;
    if (bid < 512)      { w = 64;  r = 1; }
    else if (bid < 768) { bid -= 512; w = 128; r = 2; }
    else                { bid -= 768; w = 256; r = 4; }

    const int nseg = SEQ / w;
    const int h   = bid & 7;
    const int seg = (bid >> 3) % nseg;
    const int b   = bid / (8 * nseg);
    const int base = b * SEQ + seg * w;
    const int off  = h % r;
    const int t    = threadIdx.x;
    const int lane = t & 31;
    const int wrp  = t >> 5;
    const int gid  = lane >> 2;
    const int tig  = lane & 3;

#pragma unroll
    for (int i = 0; i < 4; i++) {
        int idx = t + 128 * i;
        int j  = idx >> 3;
        int dq = (idx & 7) * 4;
        int tok = base + off + r * j;
        size_t gi = (size_t)tok * DIM + h * HDIM + dq;
        cpa16((unsigned)__cvta_generic_to_shared(&qs[j * 36 + dq]), &q[gi]);
        cpa16((unsigned)__cvta_generic_to_shared(&ks[j * 36 + dq]), &k[gi]);
        cpa16((unsigned)__cvta_generic_to_shared(&vs[j * 40 + dq]), &v[gi]);
    }
    asm volatile("cp.async.commit_group;");
    asm volatile("cp.async.wait_group 0;");
    __syncthreads();

    const int rA = wrp * 16 + gid;
    const int rB = rA + 8;
    float sacc[8][4];
#pragma unroll
    for (int nf = 0; nf < 8; nf++)
#pragma unroll
        for (int c = 0; c < 4; c++) sacc[nf][c] = 0.f;

#pragma unroll
    for (int kc = 0; kc < 4; kc++) {
        uint4 afr;
        afr.x = qs[rA * 36 + kc * 8 + tig];
        afr.y = qs[rB * 36 + kc * 8 + tig];
        afr.z = qs[rA * 36 + kc * 8 + tig + 4];
        afr.w = qs[rB * 36 + kc * 8 + tig + 4];
#pragma unroll
        for (int nf = 0; nf < 8; nf++) {
            unsigned bb0 = ks[(nf * 8 + gid) * 36 + kc * 8 + tig];
            unsigned bb1 = ks[(nf * 8 + gid) * 36 + kc * 8 + tig + 4];
            mma_tf32(sacc[nf], afr, bb0, bb1);
        }
    }

    const float scl = 0.17677669529663687f;
    float mA = -1e30f, mB = -1e30f;
#pragma unroll
    for (int nf = 0; nf < 8; nf++) {
        sacc[nf][0] *= scl; sacc[nf][1] *= scl;
        sacc[nf][2] *= scl; sacc[nf][3] *= scl;
        mA = fmaxf(mA, fmaxf(sacc[nf][0], sacc[nf][1]));
        mB = fmaxf(mB, fmaxf(sacc[nf][2], sacc[nf][3]));
    }
#pragma unroll
    for (int o = 2; o > 0; o >>= 1) {
        mA = fmaxf(mA, __shfl_xor_sync(0xffffffffu, mA, o));
        mB = fmaxf(mB, __shfl_xor_sync(0xffffffffu, mB, o));
    }
    float sA = 0.f, sB = 0.f;
#pragma unroll
    for (int nf = 0; nf < 8; nf++) {
        sacc[nf][0] = __expf(sacc[nf][0] - mA); sA += sacc[nf][0];
        sacc[nf][1] = __expf(sacc[nf][1] - mA); sA += sacc[nf][1];
        sacc[nf][2] = __expf(sacc[nf][2] - mB); sB += sacc[nf][2];
        sacc[nf][3] = __expf(sacc[nf][3] - mB); sB += sacc[nf][3];
    }
#pragma unroll
    for (int o = 2; o > 0; o >>= 1) {
        sA += __shfl_xor_sync(0xffffffffu, sA, o);
        sB += __shfl_xor_sync(0xffffffffu, sB, o);
    }
    const float iA = 1.0f / sA, iB = 1.0f / sB;

    __syncthreads();

#pragma unroll
    for (int nf = 0; nf < 8; nf++) {
        int col = nf * 8 + 2 * tig;
        uint2 pa = make_uint2(__float_as_uint(sacc[nf][0] * iA),
                              __float_as_uint(sacc[nf][1] * iA));
        uint2 pb = make_uint2(__float_as_uint(sacc[nf][2] * iB),
                              __float_as_uint(sacc[nf][3] * iB));
        *(uint2*)&smP[rA * 68 + col] = pa;
        *(uint2*)&smP[rB * 68 + col] = pb;
    }
    __syncthreads();

    float oacc[4][4];
#pragma unroll
    for (int nf = 0; nf < 4; nf++)
#pragma unroll
        for (int c = 0; c < 4; c++) oacc[nf][c] = 0.f;

#pragma unroll
    for (int kc = 0; kc < 8; kc++) {
        uint4 afr;
        afr.x = smP[rA * 68 + kc * 8 + tig];
        afr.y = smP[rB * 68 + kc * 8 + tig];
        afr.z = smP[rA * 68 + kc * 8 + tig + 4];
        afr.w = smP[rB * 68 + kc * 8 + tig + 4];
#pragma unroll
        for (int nf = 0; nf < 4; nf++) {
            unsigned bb0 = vs[(kc * 8 + tig) * 40 + nf * 8 + gid];
            unsigned bb1 = vs[(kc * 8 + tig + 4) * 40 + nf * 8 + gid];
            mma_tf32(oacc[nf], afr, bb0, bb1);
        }
    }

    const float third = 1.0f / 3.0f;
    const int tokA = base + off + r * rA;
    const int tokB = base + off + r * rB;
#pragma unroll
    for (int nf = 0; nf < 4; nf++) {
        int col = h * HDIM + nf * 8 + 2 * tig;
        float* pA = &acc[(size_t)tokA * DIM + col];
        float* pB = &acc[(size_t)tokB * DIM + col];
        atomicAdd(pA,     oacc[nf][0] * third);
        atomicAdd(pA + 1, oacc[nf][1] * third);
        atomicAdd(pB,     oacc[nf][2] * third);
        atomicAdd(pB + 1, oacc[nf][3] * third);
    }
}

// ---------------------------------------------------------------------------
// Layer-2 fused tail (per batch). Compact inputs (128 rows/batch).
// ---------------------------------------------------------------------------
__global__ __launch_bounds__(256)
void tail_kernel(const float* __restrict__ x,  const float* __restrict__ hh,
                 const float* __restrict__ k,  const float* __restrict__ v,
                 const float* __restrict__ Wq, const float* __restrict__ Wo,
                 const float* __restrict__ W1, const float* __restrict__ W2,
                 const float* __restrict__ b1v, const float* __restrict__ b2v,
                 const float* __restrict__ ln2s, const float* __restrict__ ln2b,
                 const float* __restrict__ lnfs, const float* __restrict__ lnfb,
                 float* __restrict__ out)
{
    __shared__ float xs[256], hq[256], qsh[256], att[256], x1[256], h2[256];
    __shared__ float f[1024];
    __shared__ float red[4 * 256];
    __shared__ float psh[8][64];
    __shared__ float rsum[8];

    const int b    = blockIdx.x;
    const int t    = threadIdx.x;
    const int lane = t & 31;
    const int wrp  = t >> 5;
    const size_t row0 = (size_t)b * 128 * DIM;

    xs[t] = x[row0 + t];
    hq[t] = hh[row0 + t];
    __syncthreads();

    {
        const int c4 = (t & 63) * 4;
        const int ks = t >> 6;
        float4 a = make_float4(0.f, 0.f, 0.f, 0.f);
        for (int kk = 0; kk < 64; kk++) {
            int ki = ks * 64 + kk;
            float s = hq[ki];
            float4 w = *(const float4*)&Wq[(size_t)ki * 256 + c4];
            a.x += s * w.x; a.y += s * w.y; a.z += s * w.z; a.w += s * w.w;
        }
        *(float4*)&red[ks * 256 + c4] = a;
        __syncthreads();
        qsh[t] = red[t] + red[256 + t] + red[512 + t] + red[768 + t];
        __syncthreads();
    }

    {
        const int h = wrp;
        float o = 0.f;
        const float4* qv = (const float4*)&qsh[h * 32];
#pragma unroll
        for (int c = 0; c < 3; c++) {
            const int r = 1 << c;
            if (h % r == 0) {
                int c0 = cinv(r * lane);
                int c1 = cinv(r * (lane + 32));
                const float4* k0p = (const float4*)(k + ((size_t)(b * 128 + c0) * DIM) + h * 32);
                const float4* k1p = (const float4*)(k + ((size_t)(b * 128 + c1) * DIM) + h * 32);
                float s0 = 0.f, s1 = 0.f;
#pragma unroll
                for (int u = 0; u < 8; u++) {
                    float4 qd = qv[u];
                    float4 ka = k0p[u];
                    float4 kb = k1p[u];
                    s0 += qd.x * ka.x + qd.y * ka.y + qd.z * ka.z + qd.w * ka.w;
                    s1 += qd.x * kb.x + qd.y * kb.y + qd.z * kb.z + qd.w * kb.w;
                }
                s0 *= 0.17677669529663687f;
                s1 *= 0.17677669529663687f;
                float mx = fmaxf(s0, s1);
#pragma unroll
                for (int ofs = 16; ofs > 0; ofs >>= 1)
                    mx = fmaxf(mx, __shfl_xor_sync(0xffffffffu, mx, ofs));
                float e0 = __expf(s0 - mx), e1 = __expf(s1 - mx);
                float sm = wred_sum(e0 + e1);
                float inv = 1.0f / sm;
                psh[h][lane]      = e0 * inv;
                psh[h][lane + 32] = e1 * inv;
                __syncwarp();
                float oc = 0.f;
#pragma unroll 8
                for (int j = 0; j < 64; j++) {
                    int cj = cinv(r * j);
                    oc += psh[h][j] * v[((size_t)(b * 128 + cj) * DIM) + h * 32 + lane];
                }
                o += oc;
                __syncwarp();
            }
        }
        att[h * 32 + lane] = o * (1.0f / 3.0f);
    }
    __syncthreads();

    {
        const int c4 = (t & 63) * 4;
        const int ks = t >> 6;
        float4 a = make_float4(0.f, 0.f, 0.f, 0.f);
        for (int kk = 0; kk < 64; kk++) {
            int ki = ks * 64 + kk;
            float s = att[ki];
            float4 w = *(const float4*)&Wo[(size_t)ki * 256 + c4];
            a.x += s * w.x; a.y += s * w.y; a.z += s * w.z; a.w += s * w.w;
        }
        __syncthreads();
        *(float4*)&red[ks * 256 + c4] = a;
        __syncthreads();
        x1[t] = red[t] + red[256 + t] + red[512 + t] + red[768 + t] + xs[t];
        __syncthreads();
    }

    {
        float val = x1[t];
        float s = wred_sum(val);
        if (lane == 0) rsum[wrp] = s;
        __syncthreads();
        float tot = 0.f;
#pragma unroll
        for (int i = 0; i < 8; i++) tot += rsum[i];
        float mu = tot * (1.0f / 256.0f);
        __syncthreads();
        float dv = val - mu;
        float s2 = wred_sum(dv * dv);
        if (lane == 0) rsum[wrp] = s2;
        __syncthreads();
        float tv = 0.f;
#pragma unroll
        for (int i = 0; i < 8; i++) tv += rsum[i];
        float inv = rsqrtf(tv * (1.0f / 256.0f) + 1e-5f);
        h2[t] = dv * inv * ln2s[t] + ln2b[t];
        __syncthreads();
    }

    {
        const int c4 = t * 4;
        float4 a = make_float4(0.f, 0.f, 0.f, 0.f);
        for (int ki = 0; ki < 256; ki++) {
            float s = h2[ki];
            float4 w = *(const float4*)&W1[(size_t)ki * 1024 + c4];
            a.x += s * w.x; a.y += s * w.y; a.z += s * w.z; a.w += s * w.w;
        }
        float4 bb = *(const float4*)&b1v[c4];
        f[c4 + 0] = gelu_tanh(a.x + bb.x);
        f[c4 + 1] = gelu_tanh(a.y + bb.y);
        f[c4 + 2] = gelu_tanh(a.z + bb.z);
        f[c4 + 3] = gelu_tanh(a.w + bb.w);
        __syncthreads();
    }

    {
        const int c4 = (t & 63) * 4;
        const int ks = t >> 6;
        float4 a = make_float4(0.f, 0.f, 0.f, 0.f);
        for (int kk = 0; kk < 256; kk++) {
            int ki = ks * 256 + kk;
            float s = f[ki];
            float4 w = *(const float4*)&W2[(size_t)ki * 256 + c4];
            a.x += s * w.x; a.y += s * w.y; a.z += s * w.z; a.w += s * w.w;
        }
        *(float4*)&red[ks * 256 + c4] = a;
        __syncthreads();
        float y = red[t] + red[256 + t] + red[512 + t] + red[768 + t] + b2v[t] + x1[t];

        float s = wred_sum(y);
        if (lane == 0) rsum[wrp] = s;
        __syncthreads();
        float tot = 0.f;
#pragma unroll
        for (int i = 0; i < 8; i++) tot += rsum[i];
        float mu = tot * (1.0f / 256.0f);
        __syncthreads();
        float dv = y - mu;
        float s2 = wred_sum(dv * dv);
        if (lane == 0) rsum[wrp] = s2;
        __syncthreads();
        float tv = 0.f;
#pragma unroll
        for (int i = 0; i < 8; i++) tv += rsum[i];
        float inv = rsqrtf(tv * (1.0f / 256.0f) + 1e-5f);
        out[(size_t)b * 256 + t] = dv * inv * lnfs[t] + lnfb[t];
    }
}

// ---------------------------------------------------------------------------
// Orchestration
// ---------------------------------------------------------------------------
extern "C" void kernel_launch(void* const* d_in, const int* in_sizes, int n_in,
                              void* d_out, int out_size)
{
    const float* target_feat   = (const float*)d_in[0];
    const float* context_feats = (const float*)d_in[1];
    const float* target_pos    = (const float*)d_in[2];
    const float* context_pos   = (const float*)d_in[3];
    const float* W_proj        = (const float*)d_in[4];
    const float* b_proj        = (const float*)d_in[5];
    const float* Wq            = (const float*)d_in[6];
    const float* Wk            = (const float*)d_in[7];
    const float* Wv            = (const float*)d_in[8];
    const float* Wo            = (const float*)d_in[9];
    const float* ln1_s         = (const float*)d_in[10];
    const float* ln1_b         = (const float*)d_in[11];
    const float* ln2_s         = (const float*)d_in[12];
    const float* ln2_b         = (const float*)d_in[13];
    const float* W1            = (const float*)d_in[14];
    const float* b1            = (const float*)d_in[15];
    const float* W2            = (const float*)d_in[16];
    const float* b2            = (const float*)d_in[17];
    const float* lnf_s         = (const float*)d_in[18];
    const float* lnf_b         = (const float*)d_in[19];
    float* out = (float*)d_out;

    float *x, *h, *q, *k, *v, *accb, *ffn;
    cudaGetSymbolAddress((void**)&x,    g_x);
    cudaGetSymbolAddress((void**)&h,    g_h);
    cudaGetSymbolAddress((void**)&q,    g_q);
    cudaGetSymbolAddress((void**)&k,    g_k);
    cudaGetSymbolAddress((void**)&v,    g_v);
    cudaGetSymbolAddress((void**)&accb, g_acc);
    cudaGetSymbolAddress((void**)&ffn,  g_ffn);

    // opt-in to >48KB dynamic shared memory (host-side attr, not allocation)
    static bool attr_done = false;
    if (!attr_done) {
        cudaFuncSetAttribute(gemm_pipe<5, true>,
                             cudaFuncAttributeMaxDynamicSharedMemorySize, GP_SMEM);
        cudaFuncSetAttribute(gemm_pipe<0, false>,
                             cudaFuncAttributeMaxDynamicSharedMemorySize, GP_SMEM);
        cudaFuncSetAttribute(gemm_pipe<2, false>,
                             cudaFuncAttributeMaxDynamicSharedMemorySize, GP_SMEM);
        cudaFuncSetAttribute(gemm_pipe32<6, true>,
                             cudaFuncAttributeMaxDynamicSharedMemorySize, GP32_SMEM);
        cudaFuncSetAttribute(gemm_pipe32<3, false>,
                             cudaFuncAttributeMaxDynamicSharedMemorySize, GP32_SMEM);
        cudaFuncSetAttribute(gemm_pipe32<0, false>,
                             cudaFuncAttributeMaxDynamicSharedMemorySize, GP32_SMEM);
        attr_done = true;
    }

    const dim3 gProj (DIM / 128, TOK / 64, 1);        // (2, 64)
    const dim3 gQKV  (DIM / 128, TOK / 64, 3);        // (2, 64, 3)
    const dim3 gWo   (DIM / 128, CTOK / 32, 1);       // (2, 64)
    const dim3 gFFN1 (FFN_DIM / 128, CTOK / 64, 1);   // (8, 32)
    const dim3 gFFN2 (DIM / 128, CTOK / 32, 1);       // (2, 64)
    const dim3 gKV   (DIM / 128, CTOK / 32, 2);       // (2, 64, 2)

    // 0. Zero attention accumulator
    cudaMemsetAsync(accb, 0, (size_t)TOK * DIM * sizeof(float));

    // 1. Projection (+bias +posenc), gathered A (full 4096 rows), K=512
    gemm_pipe<5, true><<<gProj, 256, GP_SMEM>>>(
        nullptr, W_proj, nullptr, nullptr, b_proj,
        x, nullptr, nullptr, DIM, INDIM,
        target_feat, context_feats, target_pos, context_pos);

    // 2. LN1 (full)
    ln_kernel<<<(TOK * 32) / 256, 256>>>(x, ln1_s, ln1_b, h, TOK, DIM);

    // 3. QKV fused (full)
    gemm_pipe<0, false><<<gQKV, 256, GP_SMEM>>>(
        h, Wq, Wk, Wv, nullptr,
        q, k, v, DIM, DIM,
        nullptr, nullptr, nullptr, nullptr);

    // 4. Attention (atomic-add into accb)
    attn_all_kernel<<<896, 128>>>(q, k, v, accb);

    // 5. Wo + residual, compact: A=acc (cmap), res=x (cmap) -> x1c (g_q)
    gemm_pipe32<6, true><<<gWo, 128, GP32_SMEM>>>(
        accb, Wo, nullptr, nullptr, x, q, nullptr, DIM, DIM);

    // 6. LN2 compact: g_q -> g_h
    ln_kernel<<<(CTOK * 32) / 256, 256>>>(q, ln2_s, ln2_b, h, CTOK, DIM);

    // 7. FFN1 compact: ffn = gelu(h @ W1 + b1)
    gemm_pipe<2, false><<<gFFN1, 256, GP_SMEM>>>(
        h, W1, nullptr, nullptr, b1,
        ffn, nullptr, nullptr, FFN_DIM, DIM,
        nullptr, nullptr, nullptr, nullptr);

    // 8. FFN2 compact: x2c = ffn @ W2 + b2 + x1c -> g_x  (K=1024)
    gemm_pipe32<3, false><<<gFFN2, 128, GP32_SMEM>>>(
        ffn, W2, nullptr, b2, q, x, nullptr, DIM, FFN_DIM);

    // 9. LN1(l2) compact: g_x -> g_h
    ln_kernel<<<(CTOK * 32) / 256, 256>>>(x, ln1_s + DIM, ln1_b + DIM, h, CTOK, DIM);

    // 10. K,V compact (z=2)
    gemm_pipe32<0, false><<<gKV, 128, GP32_SMEM>>>(
        h, Wk + DIM * DIM, Wv + DIM * DIM, nullptr, nullptr,
        k, v, DIM, DIM);

    // 11. Fused tail (compact inputs)
    tail_kernel<<<BATCH, 256>>>(
        x, h, k, v,
        Wq + DIM * DIM, Wo + DIM * DIM,
        W1 + DIM * FFN_DIM, W2 + FFN_DIM * DIM,
        b1 + FFN_DIM, b2 + DIM,
        ln2_s + DIM, ln2_b + DIM, lnf_s, lnf_b, out);
}